// round 4
// baseline (speedup 1.0000x reference)
#include <cuda_runtime.h>
#include <cuda_bf16.h>
#include <cstdint>

#define B_IMGS   32
#define NCELL    4096
#define NDET     12288
#define NCLS     80
#define TOPK     1024
#define NCAND    2048
#define NBINS    2048
#define CNF_THR  0.5f
#define IOU_THR  0.4f
#define CLS_OFF  10000.0f
#define STRIDE_S 8.0f

#define PL ((size_t)B_IMGS * NDET)

// ---------------- device scratch ----------------
__device__ float               g_det[7 * PL];                          // ~11 MB SoA
__device__ unsigned long long  g_keys[PL];                             // ~3 MB
__device__ unsigned int        g_hist[B_IMGS * NBINS];                 // 256 KB (memset 0)
__device__ unsigned int        g_cnt[B_IMGS];                          // (memset 0)
__device__ unsigned long long  g_cand[B_IMGS * NCAND];                 // 512 KB
__device__ float               g_srt[(size_t)B_IMGS * TOPK * 8];       // 1 MB (memset 0)
__device__ unsigned int        g_mask[(size_t)B_IMGS * TOPK * 32];     // 4 MB
__device__ unsigned int        g_keepw[B_IMGS * 32];

__device__ __forceinline__ unsigned int ord_f32(float f) {
    unsigned int u = __float_as_uint(f);
    return (u & 0x80000000u) ? ~u : (u | 0x80000000u);
}

// ================= K1: decode + per-image histogram =================
__global__ void __launch_bounds__(256) decode_kernel(const float* __restrict__ in) {
    __shared__ unsigned int sh_hist[NBINS];
    for (int i = threadIdx.x; i < NBINS; i += 256) sh_hist[i] = 0u;
    __syncthreads();

    const int b   = blockIdx.y;
    const int t4i = blockIdx.x * blockDim.x + threadIdx.x;   // 0..3071
    const int a   = t4i >> 10;
    const int s0  = (t4i & 1023) << 2;

    const float* p = in + ((size_t)b * 255 + (size_t)a * 85) * NCELL + s0;

    const float4 t0 = *(const float4*)(p + 0 * NCELL);
    const float4 t1 = *(const float4*)(p + 1 * NCELL);
    const float4 t2 = *(const float4*)(p + 2 * NCELL);
    const float4 t3 = *(const float4*)(p + 3 * NCELL);
    const float4 t4 = *(const float4*)(p + 4 * NCELL);

    float4 best = *(const float4*)(p + 5 * NCELL);
    int bi0 = 0, bi1 = 0, bi2 = 0, bi3 = 0;
    #pragma unroll 4
    for (int d = 1; d < NCLS; ++d) {
        const float4 v = *(const float4*)(p + (5 + d) * NCELL);
        if (v.x > best.x) { best.x = v.x; bi0 = d; }
        if (v.y > best.y) { best.y = v.y; bi1 = d; }
        if (v.z > best.z) { best.z = v.z; bi2 = d; }
        if (v.w > best.w) { best.w = v.w; bi3 = d; }
    }

    float4 o0, o1, o2, o3, o4, o5, o6;
    unsigned long long keys[4];
    float* px0 = &o0.x; float* px1 = &o1.x; float* px2 = &o2.x; float* px3 = &o3.x;
    float* px4 = &o4.x; float* px5 = &o5.x; float* px6 = &o6.x;
    const float* pt0 = &t0.x; const float* pt1 = &t1.x; const float* pt2 = &t2.x;
    const float* pt3 = &t3.x; const float* pt4 = &t4.x; const float* pb = &best.x;
    const int bis[4] = {bi0, bi1, bi2, bi3};

    #pragma unroll
    for (int e = 0; e < 4; ++e) {
        const int s = s0 + e;
        const int n = (((s & 63) << 6) | (s >> 6)) * 3 + a;   // reference order
        const float x_off = (float)((n >> 6) & 63);
        const float y_off = (float)(n & 63);

        const float cx = pt0[e] + x_off;
        const float cy = pt1[e] + y_off;
        const float hw = pt2[e] * 0.5f;
        const float hh = pt3[e] * 0.5f;
        const float conf = 1.0f / (1.0f + expf(-pt4[e]));

        px0[e] = cx - hw;  px1[e] = cy - hh;
        px2[e] = cx + hw;  px3[e] = cy + hh;
        px4[e] = conf;     px5[e] = pb[e];     px6[e] = (float)bis[e];

        const float score = (conf > CNF_THR) ? conf : (-__int_as_float(0x7f800000));
        const unsigned int hi = ord_f32(score);
        keys[e] = ((unsigned long long)hi << 32)
                | (unsigned long long)(0xFFFFFFFFu - (unsigned int)n);
        if (hi >= 0xBF000000u)
            atomicAdd(&sh_hist[(hi - 0xBF000000u) >> 12], 1u);
    }

    const size_t l = (size_t)b * NDET + (size_t)a * NCELL + s0;
    *(float4*)(g_det + 0 * PL + l) = o0;
    *(float4*)(g_det + 1 * PL + l) = o1;
    *(float4*)(g_det + 2 * PL + l) = o2;
    *(float4*)(g_det + 3 * PL + l) = o3;
    *(float4*)(g_det + 4 * PL + l) = o4;
    *(float4*)(g_det + 5 * PL + l) = o5;
    *(float4*)(g_det + 6 * PL + l) = o6;
    *(ulonglong2*)(g_keys + l)     = make_ulonglong2(keys[0], keys[1]);
    *(ulonglong2*)(g_keys + l + 2) = make_ulonglong2(keys[2], keys[3]);

    __syncthreads();
    for (int i = threadIdx.x; i < NBINS; i += 256) {
        const unsigned int v = sh_hist[i];
        if (v) atomicAdd(&g_hist[b * NBINS + i], v);
    }
}

// ================= K2: per-image threshold + compaction =================
__global__ void __launch_bounds__(1024) select_kernel() {
    __shared__ unsigned int hist[NBINS];
    __shared__ unsigned int scnt;
    __shared__ unsigned int sT;

    const int b = blockIdx.x, tid = threadIdx.x;
    hist[tid]        = g_hist[b * NBINS + tid];
    hist[tid + 1024] = g_hist[b * NBINS + tid + 1024];
    if (tid == 0) scnt = 0u;
    __syncthreads();

    // inclusive suffix sum (Hillis-Steele)
    for (int st = 1; st < NBINS; st <<= 1) {
        const unsigned int v0 = hist[tid] + ((tid + st < NBINS) ? hist[tid + st] : 0u);
        const unsigned int v1 = hist[tid + 1024] + ((tid + 1024 + st < NBINS) ? hist[tid + 1024 + st] : 0u);
        __syncthreads();
        hist[tid] = v0; hist[tid + 1024] = v1;
        __syncthreads();
    }

    if (tid == 0 && hist[0] < TOPK) sT = 0u;
    #pragma unroll
    for (int q = 0; q < 2; ++q) {
        const int bb = tid + q * 1024;
        const unsigned int sfx = hist[bb];
        const unsigned int nxt = (bb + 1 < NBINS) ? hist[bb + 1] : 0u;
        if (sfx >= TOPK && nxt < TOPK) sT = (unsigned int)bb;
    }
    __syncthreads();
    const unsigned int T = sT;

    #pragma unroll
    for (int k = 0; k < 12; ++k) {
        const unsigned long long key = g_keys[(size_t)b * NDET + tid + k * 1024];
        const unsigned int hi = (unsigned int)(key >> 32);
        if (hi >= 0xBF000000u && ((hi - 0xBF000000u) >> 12) >= T) {
            const unsigned int pos = atomicAdd(&scnt, 1u);
            if (pos < NCAND) g_cand[b * NCAND + pos] = key;
        }
    }
    __syncthreads();
    if (tid == 0) g_cnt[b] = (scnt < NCAND) ? scnt : NCAND;
}

// ================= K3: exact rank-sort + gather (chip-wide) =================
// grid (8, 32) x 256 threads; thread handles candidate i = bx*256+tid
__global__ void __launch_bounds__(256) rank_kernel() {
    __shared__ unsigned long long sk[NCAND];
    const int b = blockIdx.y;
    const int i = blockIdx.x * 256 + threadIdx.x;

    for (int t = threadIdx.x; t < NCAND; t += 256)
        sk[t] = g_cand[b * NCAND + t];
    __syncthreads();

    const int cnt = (int)g_cnt[b];
    if (i >= cnt) return;

    const unsigned long long key = sk[i];
    int rank = 0, j = 0;
    for (; j + 4 <= cnt; j += 4)
        rank += (int)(sk[j] > key) + (int)(sk[j+1] > key)
              + (int)(sk[j+2] > key) + (int)(sk[j+3] > key);
    for (; j < cnt; ++j) rank += (int)(sk[j] > key);
    if (rank >= TOPK) return;

    const unsigned int n = 0xFFFFFFFFu - (unsigned int)(key & 0xFFFFFFFFull);
    const unsigned int r = n / 3u;
    const unsigned int a = n - r * 3u;
    const unsigned int s = ((r & 63u) << 6) | (r >> 6);
    const size_t base = (size_t)b * NDET + (size_t)a * NCELL + s;

    const float c0 = g_det[0 * PL + base], c1 = g_det[1 * PL + base];
    const float c2 = g_det[2 * PL + base], c3 = g_det[3 * PL + base];
    const float c4 = g_det[4 * PL + base], c5 = g_det[5 * PL + base];
    const float c6 = g_det[6 * PL + base];

    float* o = g_srt + ((size_t)b * TOPK + rank) * 8;
    *(float4*)(o)     = make_float4(c0, c1, c2, c3);
    *(float4*)(o + 4) = make_float4(c4, c5, c6, (c2 - c0) * (c3 - c1));
}

// ================= K4: IoU suppression mask (chip-wide) =================
__device__ __forceinline__ unsigned int iou_word(
    const float4 bx, const float myA, const int q, const int w,
    const float4* __restrict__ sbox, const float* __restrict__ sarea)
{
    unsigned int bits = 0;
    const int j0 = w << 5;
    const int jlo = (j0 > q + 1) ? j0 : (q + 1);
    const int jhi = j0 + 32;
    for (int j = jlo; j < jhi; ++j) {
        const float4 ob = sbox[j];
        const float lx = fmaxf(bx.x, ob.x);
        const float ly = fmaxf(bx.y, ob.y);
        const float rx = fminf(bx.z, ob.z);
        const float ry = fminf(bx.w, ob.w);
        const float iw = fmaxf(rx - lx, 0.0f);
        const float ih = fmaxf(ry - ly, 0.0f);
        const float inter = iw * ih;
        const float iou = inter / (myA + sarea[j] - inter + 1e-9f);
        if (iou > IOU_THR) bits |= (1u << (j - j0));
    }
    return bits;
}

// grid (8, 32) x 128 threads; row q = (tid<<3)|rb (interleaved for balance)
__global__ void __launch_bounds__(128) mask_kernel() {
    __shared__ float4 sbox[TOPK];
    __shared__ float  sarea[TOPK];
    const int b = blockIdx.y, rb = blockIdx.x;

    for (int t = threadIdx.x; t < TOPK; t += 128) {
        const float* o = g_srt + ((size_t)b * TOPK + t) * 8;
        const float4 lo = *(const float4*)(o);
        const float4 hi = *(const float4*)(o + 4);
        const float sh = hi.z * CLS_OFF;
        sbox[t]  = make_float4(lo.x + sh, lo.y + sh, lo.z + sh, lo.w + sh);
        sarea[t] = hi.w;
    }
    __syncthreads();

    const int q = (threadIdx.x << 3) | rb;
    const float4 bx = sbox[q];
    const float myA = sarea[q];

    uint4* dst = (uint4*)(g_mask + ((size_t)b * TOPK + q) * 32);
    #pragma unroll
    for (int u = 0; u < 8; ++u) {
        dst[u] = make_uint4(iou_word(bx, myA, q, 4*u,   sbox, sarea),
                            iou_word(bx, myA, q, 4*u+1, sbox, sarea),
                            iou_word(bx, myA, q, 4*u+2, sbox, sarea),
                            iou_word(bx, myA, q, 4*u+3, sbox, sarea));
    }
}

// ================= K5: serial greedy (1 warp per image) =================
__global__ void __launch_bounds__(32) greedy_kernel() {
    const int b = blockIdx.x;
    const int lane = threadIdx.x;

    // valid word: lane w holds valid bits for candidates w*32..w*32+31
    unsigned int myv = 0;
    #pragma unroll
    for (int i = 0; i < 32; ++i) {
        const float conf = g_srt[((size_t)b * TOPK + i * 32 + lane) * 8 + 4];
        const unsigned int bal = __ballot_sync(0xFFFFFFFFu, conf > CNF_THR);
        if (lane == i) myv = bal;
    }

    unsigned int sup = 0;     // lane w owns suppressed word w
    unsigned int keepw = 0;   // lane blk will own keep word blk

    for (int blk = 0; blk < 32; ++blk) {
        const unsigned int ext = __shfl_sync(0xFFFFFFFFu, sup, blk);
        const unsigned int vv  = __shfl_sync(0xFFFFFFFFu, myv, blk);

        unsigned int keepmask = 0;
        if (lane == 0) {
            // diagonal block: row (blk*32+i), word blk
            const unsigned int* mrow =
                g_mask + ((size_t)b * TOPK + blk * 32) * 32 + blk;
            unsigned int rr[32];
            #pragma unroll
            for (int i = 0; i < 32; ++i) rr[i] = mrow[i * 32];
            unsigned int s = ext;
            #pragma unroll
            for (int i = 0; i < 32; ++i) {
                if (!((s >> i) & 1u) && ((vv >> i) & 1u)) {
                    keepmask |= (1u << i);
                    s |= rr[i];
                }
            }
        }
        keepmask = __shfl_sync(0xFFFFFFFFu, keepmask, 0);
        if (lane == blk) keepw = keepmask;

        // apply kept rows to global suppressed words (coalesced, predicated)
        const unsigned int* arow =
            g_mask + ((size_t)b * TOPK + blk * 32) * 32 + lane;
        #pragma unroll
        for (int i = 0; i < 32; ++i)
            if ((keepmask >> i) & 1u) sup |= arow[i * 32];
    }
    g_keepw[b * 32 + lane] = keepw;
}

// ================= K6: output =================
__global__ void __launch_bounds__(1024) output_kernel(float* __restrict__ out) {
    const int b = blockIdx.x, tid = threadIdx.x;
    const float* o = g_srt + ((size_t)b * TOPK + tid) * 8;
    const float4 lo = *(const float4*)(o);
    const float4 hi = *(const float4*)(o + 4);
    const bool kp = (g_keepw[b * 32 + (tid >> 5)] >> (tid & 31)) & 1u;
    const float f = kp ? STRIDE_S : 0.0f;
    float* od = out + ((size_t)b * TOPK + tid) * 7;
    od[0] = f * lo.x; od[1] = f * lo.y; od[2] = f * lo.z; od[3] = f * lo.w;
    od[4] = f * hi.x; od[5] = f * hi.y; od[6] = f * hi.z;
    out[(size_t)B_IMGS * TOPK * 7 + (size_t)b * TOPK + tid] = kp ? 1.0f : 0.0f;
}

// ================= launcher =================
extern "C" void kernel_launch(void* const* d_in, const int* in_sizes, int n_in,
                              void* d_out, int out_size) {
    const float* in = (const float*)d_in[0];
    float* out = (float*)d_out;

    void *p_hist = nullptr, *p_cnt = nullptr, *p_srt = nullptr;
    cudaGetSymbolAddress(&p_hist, g_hist);
    cudaGetSymbolAddress(&p_cnt,  g_cnt);
    cudaGetSymbolAddress(&p_srt,  g_srt);
    cudaMemsetAsync(p_hist, 0, (size_t)B_IMGS * NBINS * sizeof(unsigned int));
    cudaMemsetAsync(p_cnt,  0, (size_t)B_IMGS * sizeof(unsigned int));
    cudaMemsetAsync(p_srt,  0, (size_t)B_IMGS * TOPK * 8 * sizeof(float));

    decode_kernel<<<dim3(12, B_IMGS), 256>>>(in);
    select_kernel<<<B_IMGS, 1024>>>();
    rank_kernel<<<dim3(8, B_IMGS), 256>>>();
    mask_kernel<<<dim3(8, B_IMGS), 128>>>();
    greedy_kernel<<<B_IMGS, 32>>>();
    output_kernel<<<B_IMGS, 1024>>>(out);
}

// round 6
// speedup vs baseline: 2.6202x; 2.6202x over previous
#include <cuda_runtime.h>
#include <cuda_bf16.h>
#include <cstdint>

#define B_IMGS   32
#define NCELL    4096
#define NDET     12288
#define NCLS     80
#define TOPK     1024
#define NCAND    2048
#define NBINS    2048
#define CNF_THR  0.5f
#define IOU_THR  0.4f
#define CLS_OFF  10000.0f
#define STRIDE_S 8.0f

#define PL ((size_t)B_IMGS * NDET)

// ---------------- device scratch ----------------
__device__ float               g_det[7 * PL];                          // ~11 MB SoA
__device__ unsigned long long  g_keys[PL];                             // ~3 MB
__device__ unsigned int        g_hist[B_IMGS * NBINS];                 // 256 KB (memset 0)
__device__ unsigned int        g_cnt[B_IMGS];
__device__ unsigned long long  g_cand[B_IMGS * NCAND];                 // 512 KB
__device__ float               g_srt[(size_t)B_IMGS * TOPK * 8];       // 1 MB (memset 0)
__device__ unsigned int        g_mask[(size_t)B_IMGS * TOPK * 32];     // 4 MB

__device__ __forceinline__ unsigned int ord_f32(float f) {
    unsigned int u = __float_as_uint(f);
    return (u & 0x80000000u) ? ~u : (u | 0x80000000u);
}

// ================= K1: decode + per-image histogram =================
__global__ void __launch_bounds__(256) decode_kernel(const float* __restrict__ in) {
    __shared__ unsigned int sh_hist[NBINS];
    for (int i = threadIdx.x; i < NBINS; i += 256) sh_hist[i] = 0u;
    __syncthreads();

    const int b   = blockIdx.y;
    const int t4i = blockIdx.x * blockDim.x + threadIdx.x;   // 0..3071
    const int a   = t4i >> 10;
    const int s0  = (t4i & 1023) << 2;

    const float* p = in + ((size_t)b * 255 + (size_t)a * 85) * NCELL + s0;

    const float4 t0 = *(const float4*)(p + 0 * NCELL);
    const float4 t1 = *(const float4*)(p + 1 * NCELL);
    const float4 t2 = *(const float4*)(p + 2 * NCELL);
    const float4 t3 = *(const float4*)(p + 3 * NCELL);
    const float4 t4 = *(const float4*)(p + 4 * NCELL);

    float4 best = *(const float4*)(p + 5 * NCELL);
    int bi0 = 0, bi1 = 0, bi2 = 0, bi3 = 0;
    #pragma unroll 4
    for (int d = 1; d < NCLS; ++d) {
        const float4 v = *(const float4*)(p + (5 + d) * NCELL);
        if (v.x > best.x) { best.x = v.x; bi0 = d; }
        if (v.y > best.y) { best.y = v.y; bi1 = d; }
        if (v.z > best.z) { best.z = v.z; bi2 = d; }
        if (v.w > best.w) { best.w = v.w; bi3 = d; }
    }

    float4 o0, o1, o2, o3, o4, o5, o6;
    unsigned long long keys[4];
    float* px0 = &o0.x; float* px1 = &o1.x; float* px2 = &o2.x; float* px3 = &o3.x;
    float* px4 = &o4.x; float* px5 = &o5.x; float* px6 = &o6.x;
    const float* pt0 = &t0.x; const float* pt1 = &t1.x; const float* pt2 = &t2.x;
    const float* pt3 = &t3.x; const float* pt4 = &t4.x; const float* pb = &best.x;
    const int bis[4] = {bi0, bi1, bi2, bi3};

    #pragma unroll
    for (int e = 0; e < 4; ++e) {
        const int s = s0 + e;
        const int n = (((s & 63) << 6) | (s >> 6)) * 3 + a;   // reference order
        const float x_off = (float)((n >> 6) & 63);
        const float y_off = (float)(n & 63);

        const float cx = pt0[e] + x_off;
        const float cy = pt1[e] + y_off;
        const float hw = pt2[e] * 0.5f;
        const float hh = pt3[e] * 0.5f;
        const float conf = 1.0f / (1.0f + expf(-pt4[e]));

        px0[e] = cx - hw;  px1[e] = cy - hh;
        px2[e] = cx + hw;  px3[e] = cy + hh;
        px4[e] = conf;     px5[e] = pb[e];     px6[e] = (float)bis[e];

        const float score = (conf > CNF_THR) ? conf : (-__int_as_float(0x7f800000));
        const unsigned int hi = ord_f32(score);
        keys[e] = ((unsigned long long)hi << 32)
                | (unsigned long long)(0xFFFFFFFFu - (unsigned int)n);
        if (hi >= 0xBF000000u)
            atomicAdd(&sh_hist[(hi - 0xBF000000u) >> 12], 1u);
    }

    const size_t l = (size_t)b * NDET + (size_t)a * NCELL + s0;
    *(float4*)(g_det + 0 * PL + l) = o0;
    *(float4*)(g_det + 1 * PL + l) = o1;
    *(float4*)(g_det + 2 * PL + l) = o2;
    *(float4*)(g_det + 3 * PL + l) = o3;
    *(float4*)(g_det + 4 * PL + l) = o4;
    *(float4*)(g_det + 5 * PL + l) = o5;
    *(float4*)(g_det + 6 * PL + l) = o6;
    *(ulonglong2*)(g_keys + l)     = make_ulonglong2(keys[0], keys[1]);
    *(ulonglong2*)(g_keys + l + 2) = make_ulonglong2(keys[2], keys[3]);

    __syncthreads();
    for (int i = threadIdx.x; i < NBINS; i += 256) {
        const unsigned int v = sh_hist[i];
        if (v) atomicAdd(&g_hist[b * NBINS + i], v);
    }
}

// ================= K2: per-image threshold + compaction =================
__global__ void __launch_bounds__(1024) select_kernel() {
    __shared__ unsigned int hist[NBINS];
    __shared__ unsigned int scnt;
    __shared__ unsigned int sT;

    const int b = blockIdx.x, tid = threadIdx.x;
    hist[tid]        = g_hist[b * NBINS + tid];
    hist[tid + 1024] = g_hist[b * NBINS + tid + 1024];
    if (tid == 0) scnt = 0u;
    __syncthreads();

    for (int st = 1; st < NBINS; st <<= 1) {
        const unsigned int v0 = hist[tid] + ((tid + st < NBINS) ? hist[tid + st] : 0u);
        const unsigned int v1 = hist[tid + 1024] + ((tid + 1024 + st < NBINS) ? hist[tid + 1024 + st] : 0u);
        __syncthreads();
        hist[tid] = v0; hist[tid + 1024] = v1;
        __syncthreads();
    }

    if (tid == 0 && hist[0] < TOPK) sT = 0u;
    #pragma unroll
    for (int q = 0; q < 2; ++q) {
        const int bb = tid + q * 1024;
        const unsigned int sfx = hist[bb];
        const unsigned int nxt = (bb + 1 < NBINS) ? hist[bb + 1] : 0u;
        if (sfx >= TOPK && nxt < TOPK) sT = (unsigned int)bb;
    }
    __syncthreads();
    const unsigned int T = sT;

    #pragma unroll
    for (int k = 0; k < 12; ++k) {
        const unsigned long long key = g_keys[(size_t)b * NDET + tid + k * 1024];
        const unsigned int hi = (unsigned int)(key >> 32);
        if (hi >= 0xBF000000u && ((hi - 0xBF000000u) >> 12) >= T) {
            const unsigned int pos = atomicAdd(&scnt, 1u);
            if (pos < NCAND) g_cand[b * NCAND + pos] = key;
        }
    }
    __syncthreads();
    if (tid == 0) g_cnt[b] = (scnt < NCAND) ? scnt : NCAND;
}

// ================= K3: exact rank-sort + gather =================
__global__ void __launch_bounds__(256) rank_kernel() {
    __shared__ unsigned long long sk[NCAND];
    const int b = blockIdx.y;
    const int i = blockIdx.x * 256 + threadIdx.x;

    for (int t = threadIdx.x; t < NCAND; t += 256)
        sk[t] = g_cand[b * NCAND + t];
    __syncthreads();

    const int cnt = (int)g_cnt[b];
    if (i >= cnt) return;

    const unsigned long long key = sk[i];
    int rank = 0, j = 0;
    for (; j + 4 <= cnt; j += 4)
        rank += (int)(sk[j] > key) + (int)(sk[j+1] > key)
              + (int)(sk[j+2] > key) + (int)(sk[j+3] > key);
    for (; j < cnt; ++j) rank += (int)(sk[j] > key);
    if (rank >= TOPK) return;

    const unsigned int n = 0xFFFFFFFFu - (unsigned int)(key & 0xFFFFFFFFull);
    const unsigned int r = n / 3u;
    const unsigned int a = n - r * 3u;
    const unsigned int s = ((r & 63u) << 6) | (r >> 6);
    const size_t base = (size_t)b * NDET + (size_t)a * NCELL + s;

    const float c0 = g_det[0 * PL + base], c1 = g_det[1 * PL + base];
    const float c2 = g_det[2 * PL + base], c3 = g_det[3 * PL + base];
    const float c4 = g_det[4 * PL + base], c5 = g_det[5 * PL + base];
    const float c6 = g_det[6 * PL + base];

    float* o = g_srt + ((size_t)b * TOPK + rank) * 8;
    *(float4*)(o)     = make_float4(c0, c1, c2, c3);
    *(float4*)(o + 4) = make_float4(c4, c5, c6, (c2 - c0) * (c3 - c1));
}

// ================= K4: IoU mask — 1 word per thread, chip-wide =================
// grid (32 qblk, 32 img) x 1024; tid = (w<<5)|q_local -> warp = 32 rows, same word
__global__ void __launch_bounds__(1024) mask_kernel() {
    __shared__ float4 sbox[TOPK];   // 16 KB
    __shared__ float  sarea[TOPK];  //  4 KB
    const int b = blockIdx.y;
    const int tid = threadIdx.x;

    for (int t = tid; t < TOPK; t += 1024) {
        const float* o = g_srt + ((size_t)b * TOPK + t) * 8;
        const float4 lo = *(const float4*)(o);
        const float4 hi = *(const float4*)(o + 4);
        const float sh = hi.z * CLS_OFF;
        sbox[t]  = make_float4(lo.x + sh, lo.y + sh, lo.z + sh, lo.w + sh);
        sarea[t] = hi.w;
    }
    __syncthreads();

    const int q = (blockIdx.x << 5) | (tid & 31);
    const int w = tid >> 5;
    const int j0 = w << 5;

    unsigned int bits = 0;
    if (j0 + 31 > q) {                     // skip strictly-lower-triangle words
        const float4 bx  = sbox[q];
        const float  myA = sarea[q];
        const int jlo = (j0 > q + 1) ? j0 : (q + 1);
        for (int j = jlo; j < j0 + 32; ++j) {
            const float4 ob = sbox[j];
            const float lx = fmaxf(bx.x, ob.x);
            const float ly = fmaxf(bx.y, ob.y);
            const float rx = fminf(bx.z, ob.z);
            const float ry = fminf(bx.w, ob.w);
            const float iw = fmaxf(rx - lx, 0.0f);
            const float ih = fmaxf(ry - ly, 0.0f);
            const float inter = iw * ih;
            const float iou = inter / (myA + sarea[j] - inter + 1e-9f);
            if (iou > IOU_THR) bits |= (1u << (j - j0));
        }
    }
    g_mask[((size_t)b * TOPK + q) * 32 + w] = bits;
}

// ================= K5: greedy (mask staged in smem) + output =================
#define GREEDY_SMEM (TOPK * 32 * 4)   // 128 KB
__global__ void __launch_bounds__(1024) greedy_kernel(float* __restrict__ out) {
    extern __shared__ unsigned int smask[];       // [TOPK*32]
    __shared__ unsigned int svalid[32];
    __shared__ unsigned int skeepw[32];

    const int b = blockIdx.x, tid = threadIdx.x;

    // stage full mask (128 KB) into smem
    const uint4* src = (const uint4*)(g_mask + (size_t)b * TOPK * 32);
    uint4* dst = (uint4*)smask;
    #pragma unroll
    for (int k = 0; k < 8; ++k) dst[tid + k * 1024] = src[tid + k * 1024];

    // candidate data + valid ballot
    const float* o = g_srt + ((size_t)b * TOPK + tid) * 8;
    const float4 lo = *(const float4*)(o);
    const float4 hi = *(const float4*)(o + 4);
    const unsigned int bal = __ballot_sync(0xFFFFFFFFu, hi.x > CNF_THR);
    if ((tid & 31) == 0) svalid[tid >> 5] = bal;
    __syncthreads();

    // serial greedy: warp 0, lane w owns suppressed word w
    if (tid < 32) {
        const int lane = tid;
        unsigned int sup = 0, keepw = 0;
        for (int blk = 0; blk < 32; ++blk) {
            const unsigned int ext = __shfl_sync(0xFFFFFFFFu, sup, blk);
            const unsigned int vv  = svalid[blk];

            unsigned int keepmask = 0;
            if (lane == 0) {
                unsigned int rr[32];
                #pragma unroll
                for (int i = 0; i < 32; ++i)
                    rr[i] = smask[(blk * 32 + i) * 32 + blk];
                unsigned int s = ext;
                #pragma unroll
                for (int i = 0; i < 32; ++i) {
                    if (!((s >> i) & 1u) && ((vv >> i) & 1u)) {
                        keepmask |= (1u << i);
                        s |= rr[i];
                    }
                }
            }
            keepmask = __shfl_sync(0xFFFFFFFFu, keepmask, 0);
            if (lane == blk) keepw = keepmask;

            #pragma unroll
            for (int i = 0; i < 32; ++i)
                if ((keepmask >> i) & 1u) sup |= smask[(blk * 32 + i) * 32 + lane];
        }
        skeepw[lane] = keepw;
    }
    __syncthreads();

    // output
    const bool kp = (skeepw[tid >> 5] >> (tid & 31)) & 1u;
    const float f = kp ? STRIDE_S : 0.0f;
    float* od = out + ((size_t)b * TOPK + tid) * 7;
    od[0] = f * lo.x; od[1] = f * lo.y; od[2] = f * lo.z; od[3] = f * lo.w;
    od[4] = f * hi.x; od[5] = f * hi.y; od[6] = f * hi.z;
    out[(size_t)B_IMGS * TOPK * 7 + (size_t)b * TOPK + tid] = kp ? 1.0f : 0.0f;
}

// ================= launcher =================
extern "C" void kernel_launch(void* const* d_in, const int* in_sizes, int n_in,
                              void* d_out, int out_size) {
    const float* in = (const float*)d_in[0];
    float* out = (float*)d_out;

    cudaFuncSetAttribute(greedy_kernel, cudaFuncAttributeMaxDynamicSharedMemorySize,
                         GREEDY_SMEM);

    void *p_hist = nullptr, *p_srt = nullptr;
    cudaGetSymbolAddress(&p_hist, g_hist);
    cudaGetSymbolAddress(&p_srt,  g_srt);
    cudaMemsetAsync(p_hist, 0, (size_t)B_IMGS * NBINS * sizeof(unsigned int));
    cudaMemsetAsync(p_srt,  0, (size_t)B_IMGS * TOPK * 8 * sizeof(float));

    decode_kernel<<<dim3(12, B_IMGS), 256>>>(in);
    select_kernel<<<B_IMGS, 1024>>>();
    rank_kernel<<<dim3(8, B_IMGS), 256>>>();
    mask_kernel<<<dim3(32, B_IMGS), 1024>>>();
    greedy_kernel<<<B_IMGS, 1024, GREEDY_SMEM>>>(out);
}

// round 8
// speedup vs baseline: 3.2330x; 1.2339x over previous
#include <cuda_runtime.h>
#include <cuda_bf16.h>
#include <cstdint>

#define B_IMGS   32
#define NCELL    4096
#define NDET     12288
#define NCLS     80
#define TOPK     1024
#define NCAND    2048
#define NBINS    2048
#define CNF_THR  0.5f
#define IOU_THR  0.4f
#define CLS_OFF  10000.0f
#define STRIDE_S 8.0f
#define NPAIRS   528              // upper-triangle (qblock, word) pairs per image

#define PL ((size_t)B_IMGS * NDET)

// ---------------- device scratch ----------------
__device__ float               g_det[7 * PL];                          // ~11 MB SoA
__device__ unsigned long long  g_keys[PL];                             // ~3 MB
__device__ unsigned int        g_hist[B_IMGS * NBINS];                 // 256 KB (memset 0)
__device__ unsigned int        g_cnt[B_IMGS];
__device__ unsigned long long  g_cand[B_IMGS * NCAND];                 // 512 KB
__device__ float               g_srt[(size_t)B_IMGS * TOPK * 8];       // 1 MB (memset 0)
__device__ unsigned int        g_mask[(size_t)B_IMGS * TOPK * 32];     // 4 MB (upper-tri only)

__device__ __forceinline__ unsigned int ord_f32(float f) {
    unsigned int u = __float_as_uint(f);
    return (u & 0x80000000u) ? ~u : (u | 0x80000000u);
}

__device__ __forceinline__ int tri_off(int qb) { return 32 * qb - (qb * (qb - 1)) / 2; }

// ================= K1: decode + per-image histogram =================
__global__ void __launch_bounds__(256) decode_kernel(const float* __restrict__ in) {
    __shared__ unsigned int sh_hist[NBINS];
    for (int i = threadIdx.x; i < NBINS; i += 256) sh_hist[i] = 0u;
    __syncthreads();

    const int b   = blockIdx.y;
    const int t4i = blockIdx.x * blockDim.x + threadIdx.x;   // 0..3071
    const int a   = t4i >> 10;
    const int s0  = (t4i & 1023) << 2;

    const float* p = in + ((size_t)b * 255 + (size_t)a * 85) * NCELL + s0;

    const float4 t0 = *(const float4*)(p + 0 * NCELL);
    const float4 t1 = *(const float4*)(p + 1 * NCELL);
    const float4 t2 = *(const float4*)(p + 2 * NCELL);
    const float4 t3 = *(const float4*)(p + 3 * NCELL);
    const float4 t4 = *(const float4*)(p + 4 * NCELL);

    float4 best = *(const float4*)(p + 5 * NCELL);
    int bi0 = 0, bi1 = 0, bi2 = 0, bi3 = 0;
    #pragma unroll 4
    for (int d = 1; d < NCLS; ++d) {
        const float4 v = *(const float4*)(p + (5 + d) * NCELL);
        if (v.x > best.x) { best.x = v.x; bi0 = d; }
        if (v.y > best.y) { best.y = v.y; bi1 = d; }
        if (v.z > best.z) { best.z = v.z; bi2 = d; }
        if (v.w > best.w) { best.w = v.w; bi3 = d; }
    }

    float4 o0, o1, o2, o3, o4, o5, o6;
    unsigned long long keys[4];
    float* px0 = &o0.x; float* px1 = &o1.x; float* px2 = &o2.x; float* px3 = &o3.x;
    float* px4 = &o4.x; float* px5 = &o5.x; float* px6 = &o6.x;
    const float* pt0 = &t0.x; const float* pt1 = &t1.x; const float* pt2 = &t2.x;
    const float* pt3 = &t3.x; const float* pt4 = &t4.x; const float* pb = &best.x;
    const int bis[4] = {bi0, bi1, bi2, bi3};

    #pragma unroll
    for (int e = 0; e < 4; ++e) {
        const int s = s0 + e;
        const int n = (((s & 63) << 6) | (s >> 6)) * 3 + a;   // reference order
        const float x_off = (float)((n >> 6) & 63);
        const float y_off = (float)(n & 63);

        const float cx = pt0[e] + x_off;
        const float cy = pt1[e] + y_off;
        const float hw = pt2[e] * 0.5f;
        const float hh = pt3[e] * 0.5f;
        const float conf = 1.0f / (1.0f + expf(-pt4[e]));

        px0[e] = cx - hw;  px1[e] = cy - hh;
        px2[e] = cx + hw;  px3[e] = cy + hh;
        px4[e] = conf;     px5[e] = pb[e];     px6[e] = (float)bis[e];

        const float score = (conf > CNF_THR) ? conf : (-__int_as_float(0x7f800000));
        const unsigned int hi = ord_f32(score);
        keys[e] = ((unsigned long long)hi << 32)
                | (unsigned long long)(0xFFFFFFFFu - (unsigned int)n);
        if (hi >= 0xBF000000u)
            atomicAdd(&sh_hist[(hi - 0xBF000000u) >> 12], 1u);
    }

    const size_t l = (size_t)b * NDET + (size_t)a * NCELL + s0;
    *(float4*)(g_det + 0 * PL + l) = o0;
    *(float4*)(g_det + 1 * PL + l) = o1;
    *(float4*)(g_det + 2 * PL + l) = o2;
    *(float4*)(g_det + 3 * PL + l) = o3;
    *(float4*)(g_det + 4 * PL + l) = o4;
    *(float4*)(g_det + 5 * PL + l) = o5;
    *(float4*)(g_det + 6 * PL + l) = o6;
    *(ulonglong2*)(g_keys + l)     = make_ulonglong2(keys[0], keys[1]);
    *(ulonglong2*)(g_keys + l + 2) = make_ulonglong2(keys[2], keys[3]);

    __syncthreads();
    for (int i = threadIdx.x; i < NBINS; i += 256) {
        const unsigned int v = sh_hist[i];
        if (v) atomicAdd(&g_hist[b * NBINS + i], v);
    }
}

// ================= K2: per-image threshold + compaction =================
__global__ void __launch_bounds__(1024) select_kernel() {
    __shared__ unsigned int hist[NBINS];
    __shared__ unsigned int scnt;
    __shared__ unsigned int sT;

    const int b = blockIdx.x, tid = threadIdx.x;
    hist[tid]        = g_hist[b * NBINS + tid];
    hist[tid + 1024] = g_hist[b * NBINS + tid + 1024];
    if (tid == 0) scnt = 0u;
    __syncthreads();

    for (int st = 1; st < NBINS; st <<= 1) {
        const unsigned int v0 = hist[tid] + ((tid + st < NBINS) ? hist[tid + st] : 0u);
        const unsigned int v1 = hist[tid + 1024] + ((tid + 1024 + st < NBINS) ? hist[tid + 1024 + st] : 0u);
        __syncthreads();
        hist[tid] = v0; hist[tid + 1024] = v1;
        __syncthreads();
    }

    if (tid == 0 && hist[0] < TOPK) sT = 0u;
    #pragma unroll
    for (int q = 0; q < 2; ++q) {
        const int bb = tid + q * 1024;
        const unsigned int sfx = hist[bb];
        const unsigned int nxt = (bb + 1 < NBINS) ? hist[bb + 1] : 0u;
        if (sfx >= TOPK && nxt < TOPK) sT = (unsigned int)bb;
    }
    __syncthreads();
    const unsigned int T = sT;

    #pragma unroll
    for (int k = 0; k < 12; ++k) {
        const unsigned long long key = g_keys[(size_t)b * NDET + tid + k * 1024];
        const unsigned int hi = (unsigned int)(key >> 32);
        if (hi >= 0xBF000000u && ((hi - 0xBF000000u) >> 12) >= T) {
            const unsigned int pos = atomicAdd(&scnt, 1u);
            if (pos < NCAND) g_cand[b * NCAND + pos] = key;
        }
    }
    __syncthreads();
    if (tid == 0) g_cnt[b] = (scnt < NCAND) ? scnt : NCAND;
}

// ================= K3: exact rank-sort + gather =================
__global__ void __launch_bounds__(256) rank_kernel() {
    __shared__ unsigned long long sk[NCAND];
    const int b = blockIdx.y;
    const int i = blockIdx.x * 256 + threadIdx.x;

    for (int t = threadIdx.x; t < NCAND; t += 256)
        sk[t] = g_cand[b * NCAND + t];
    __syncthreads();

    const int cnt = (int)g_cnt[b];
    if (i >= cnt) return;

    const unsigned long long key = sk[i];
    int rank = 0, j = 0;
    for (; j + 4 <= cnt; j += 4)
        rank += (int)(sk[j] > key) + (int)(sk[j+1] > key)
              + (int)(sk[j+2] > key) + (int)(sk[j+3] > key);
    for (; j < cnt; ++j) rank += (int)(sk[j] > key);
    if (rank >= TOPK) return;

    const unsigned int n = 0xFFFFFFFFu - (unsigned int)(key & 0xFFFFFFFFull);
    const unsigned int r = n / 3u;
    const unsigned int a = n - r * 3u;
    const unsigned int s = ((r & 63u) << 6) | (r >> 6);
    const size_t base = (size_t)b * NDET + (size_t)a * NCELL + s;

    const float c0 = g_det[0 * PL + base], c1 = g_det[1 * PL + base];
    const float c2 = g_det[2 * PL + base], c3 = g_det[3 * PL + base];
    const float c4 = g_det[4 * PL + base], c5 = g_det[5 * PL + base];
    const float c6 = g_det[6 * PL + base];

    float* o = g_srt + ((size_t)b * TOPK + rank) * 8;
    *(float4*)(o)     = make_float4(c0, c1, c2, c3);
    *(float4*)(o + 4) = make_float4(c4, c5, c6, (c2 - c0) * (c3 - c1));
}

// ================= K4: IoU mask — upper-triangle pairs only =================
// One warp per (qblock, word) pair, lane = row within qblock. grid (17, 32) x 1024.
__global__ void __launch_bounds__(1024) mask_kernel() {
    __shared__ float4 sbox[TOPK];   // 16 KB
    __shared__ float  sarea[TOPK];  //  4 KB
    const int b = blockIdx.y;
    const int tid = threadIdx.x;

    for (int t = tid; t < TOPK; t += 1024) {
        const float* o = g_srt + ((size_t)b * TOPK + t) * 8;
        const float4 lo = *(const float4*)(o);
        const float4 hi = *(const float4*)(o + 4);
        const float sh = hi.z * CLS_OFF;
        sbox[t]  = make_float4(lo.x + sh, lo.y + sh, lo.z + sh, lo.w + sh);
        sarea[t] = hi.w;
    }
    __syncthreads();

    const int p = blockIdx.x * 32 + (tid >> 5);   // pair index
    if (p >= NPAIRS) return;

    // decode triangular pair index -> (qb, w), w >= qb
    const float rt = sqrtf(4225.0f - 8.0f * (float)p);
    int qb = (int)((65.0f - rt) * 0.5f);
    if (tri_off(qb + 1) <= p) qb++;
    if (tri_off(qb) > p) qb--;
    const int w = qb + (p - tri_off(qb));
    const int q = (qb << 5) | (tid & 31);

    const float4 bx  = sbox[q];
    const float  myA = sarea[q];
    const int j0 = w << 5;

    unsigned int bits = 0;
    #pragma unroll 8
    for (int jj = 0; jj < 32; ++jj) {
        const int j = j0 + jj;
        const float4 ob = sbox[j];
        const float lx = fmaxf(bx.x, ob.x);
        const float ly = fmaxf(bx.y, ob.y);
        const float rx = fminf(bx.z, ob.z);
        const float ry = fminf(bx.w, ob.w);
        const float iw = fmaxf(rx - lx, 0.0f);
        const float ih = fmaxf(ry - ly, 0.0f);
        const float inter = iw * ih;
        const float denom = myA + sarea[j] - inter + 1e-9f;
        // iou > thr  <=>  denom > 0 && inter > thr*denom   (no divide)
        const bool hit = (denom > 0.0f) && (inter > IOU_THR * denom) && (j > q);
        if (hit) bits |= (1u << jj);
    }
    g_mask[((size_t)b * TOPK + q) * 32 + w] = bits;
}

// ================= K5: greedy (mask staged in smem) + output =================
#define GREEDY_SMEM (TOPK * 32 * 4)   // 128 KB
__global__ void __launch_bounds__(1024) greedy_kernel(float* __restrict__ out) {
    extern __shared__ unsigned int smask[];       // [TOPK*32]
    __shared__ unsigned int svalid[32];
    __shared__ unsigned int skeepw[32];

    const int b = blockIdx.x, tid = threadIdx.x;

    // stage full mask (128 KB) into smem
    const uint4* src = (const uint4*)(g_mask + (size_t)b * TOPK * 32);
    uint4* dst = (uint4*)smask;
    #pragma unroll
    for (int k = 0; k < 8; ++k) dst[tid + k * 1024] = src[tid + k * 1024];

    // candidate data + valid ballot
    const float* o = g_srt + ((size_t)b * TOPK + tid) * 8;
    const float4 lo = *(const float4*)(o);
    const float4 hi = *(const float4*)(o + 4);
    const unsigned int bal = __ballot_sync(0xFFFFFFFFu, hi.x > CNF_THR);
    if ((tid & 31) == 0) svalid[tid >> 5] = bal;
    __syncthreads();

    // serial greedy: warp 0, lane w owns suppressed word w
    if (tid < 32) {
        const int lane = tid;
        unsigned int sup = 0, keepw = 0;
        for (int blk = 0; blk < 32; ++blk) {
            const unsigned int ext = __shfl_sync(0xFFFFFFFFu, sup, blk);
            const unsigned int vv  = svalid[blk];

            unsigned int keepmask = 0;
            if (lane == 0) {
                unsigned int rr[32];
                #pragma unroll
                for (int i = 0; i < 32; ++i)
                    rr[i] = smask[(blk * 32 + i) * 32 + blk];
                unsigned int s = ext;
                #pragma unroll
                for (int i = 0; i < 32; ++i) {
                    if (!((s >> i) & 1u) && ((vv >> i) & 1u)) {
                        keepmask |= (1u << i);
                        s |= rr[i];
                    }
                }
            }
            keepmask = __shfl_sync(0xFFFFFFFFu, keepmask, 0);
            if (lane == blk) keepw = keepmask;

            // only upper-triangle words (lane >= blk) were written; lower are implicitly 0
            if (lane >= blk) {
                #pragma unroll
                for (int i = 0; i < 32; ++i)
                    if ((keepmask >> i) & 1u) sup |= smask[(blk * 32 + i) * 32 + lane];
            }
        }
        skeepw[lane] = keepw;
    }
    __syncthreads();

    // output
    const bool kp = (skeepw[tid >> 5] >> (tid & 31)) & 1u;
    const float f = kp ? STRIDE_S : 0.0f;
    float* od = out + ((size_t)b * TOPK + tid) * 7;
    od[0] = f * lo.x; od[1] = f * lo.y; od[2] = f * lo.z; od[3] = f * lo.w;
    od[4] = f * hi.x; od[5] = f * hi.y; od[6] = f * hi.z;
    out[(size_t)B_IMGS * TOPK * 7 + (size_t)b * TOPK + tid] = kp ? 1.0f : 0.0f;
}

// ================= launcher =================
extern "C" void kernel_launch(void* const* d_in, const int* in_sizes, int n_in,
                              void* d_out, int out_size) {
    const float* in = (const float*)d_in[0];
    float* out = (float*)d_out;

    cudaFuncSetAttribute(greedy_kernel, cudaFuncAttributeMaxDynamicSharedMemorySize,
                         GREEDY_SMEM);

    void *p_hist = nullptr, *p_srt = nullptr;
    cudaGetSymbolAddress(&p_hist, g_hist);
    cudaGetSymbolAddress(&p_srt,  g_srt);
    cudaMemsetAsync(p_hist, 0, (size_t)B_IMGS * NBINS * sizeof(unsigned int));
    cudaMemsetAsync(p_srt,  0, (size_t)B_IMGS * TOPK * 8 * sizeof(float));

    decode_kernel<<<dim3(12, B_IMGS), 256>>>(in);
    select_kernel<<<B_IMGS, 1024>>>();
    rank_kernel<<<dim3(8, B_IMGS), 256>>>();
    mask_kernel<<<dim3((NPAIRS + 31) / 32, B_IMGS), 1024>>>();
    greedy_kernel<<<B_IMGS, 1024, GREEDY_SMEM>>>(out);
}

// round 9
// speedup vs baseline: 3.5382x; 1.0944x over previous
#include <cuda_runtime.h>
#include <cuda_bf16.h>
#include <cstdint>

#define B_IMGS   32
#define NCELL    4096
#define NDET     12288
#define NCLS     80
#define TOPK     1024
#define NCAND    2048
#define NBINS    256
#define CNF_THR  0.5f
#define IOU_THR  0.4f
#define CLS_OFF  10000.0f
#define STRIDE_S 8.0f
#define NPAIRS   528              // upper-triangle (qblock, word) pairs per image

// ---------------- device scratch ----------------
__device__ unsigned long long  g_keys[(size_t)B_IMGS * NDET];          // 3 MB
__device__ unsigned int        g_hist[B_IMGS * NBINS];                 // zeroed by greedy tail
__device__ unsigned int        g_cnt[B_IMGS];                          // zeroed by greedy tail
__device__ unsigned long long  g_cand[B_IMGS * NCAND];                 // 512 KB
__device__ float               g_srt[(size_t)B_IMGS * TOPK * 8];       // 1 MB
__device__ float4              g_box[(size_t)B_IMGS * TOPK];           // shifted boxes
__device__ float               g_area[(size_t)B_IMGS * TOPK];
__device__ unsigned int        g_mask[(size_t)B_IMGS * TOPK * 32];     // 4 MB (upper-tri only)

__device__ __forceinline__ unsigned int ord_f32(float f) {
    unsigned int u = __float_as_uint(f);
    return (u & 0x80000000u) ? ~u : (u | 0x80000000u);
}

__device__ __forceinline__ int tri_off(int qb) { return 32 * qb - (qb * (qb - 1)) / 2; }

// ================= K1: objectness-only keys + histogram =================
// grid (12, 32) x 1024; thread -> det l = a*4096 + s of image b. Reads ONLY channel 4.
__global__ void __launch_bounds__(1024) conf_kernel(const float* __restrict__ in) {
    __shared__ unsigned int sh[NBINS];
    const int tid = threadIdx.x;
    if (tid < NBINS) sh[tid] = 0u;
    __syncthreads();

    const int b = blockIdx.y;
    const int l = blockIdx.x * 1024 + tid;     // 0..12287
    const int a = l >> 12;
    const int s = l & 4095;

    const float t4 = in[((size_t)b * 255 + (size_t)a * 85 + 4) * NCELL + s];
    const float conf = 1.0f / (1.0f + expf(-t4));

    const int n = (((s & 63) << 6) | (s >> 6)) * 3 + a;   // reference det order
    const float score = (conf > CNF_THR) ? conf : (-__int_as_float(0x7f800000));
    const unsigned int hi = ord_f32(score);
    g_keys[(size_t)b * NDET + l] =
        ((unsigned long long)hi << 32) | (unsigned long long)(0xFFFFFFFFu - (unsigned int)n);

    if (hi >= 0xBF000000u) {
        unsigned int bin = (hi - 0xBF000000u) >> 15;
        if (bin > 255u) bin = 255u;
        atomicAdd(&sh[bin], 1u);
    }
    __syncthreads();
    if (tid < NBINS) {
        const unsigned int v = sh[tid];
        if (v) atomicAdd(&g_hist[b * NBINS + tid], v);
    }
}

// ================= K2: threshold (warp-scan) + chip-wide compaction =================
// grid (12, 32) x 1024; warp 0 computes T; every thread tests one key.
__global__ void __launch_bounds__(1024) compact_kernel() {
    __shared__ unsigned int sT;
    const int b = blockIdx.y, tid = threadIdx.x;

    if (tid < 32) {
        const int lane = tid;
        unsigned int v[8];
        #pragma unroll
        for (int k = 0; k < 8; ++k) v[k] = g_hist[b * NBINS + lane * 8 + k];
        unsigned int ls[9];
        ls[8] = 0u;
        #pragma unroll
        for (int k = 7; k >= 0; --k) ls[k] = ls[k + 1] + v[k];
        const unsigned int t = ls[0];
        unsigned int st = t;
        #pragma unroll
        for (int off = 1; off < 32; off <<= 1) {
            const unsigned int nn = __shfl_down_sync(0xFFFFFFFFu, st, off);
            if (lane + off < 32) st += nn;
        }
        const unsigned int after = st - t;   // suffix over lanes > lane
        if (lane == 0) sT = 0u;
        __syncwarp();
        #pragma unroll
        for (int k = 0; k < 8; ++k) {
            const unsigned int sfx = ls[k] + after;
            const unsigned int nxt = ls[k + 1] + after;
            if (sfx >= TOPK && nxt < TOPK) sT = (unsigned int)(lane * 8 + k);
        }
    }
    __syncthreads();
    const unsigned int T = sT;

    const unsigned long long key = g_keys[(size_t)b * NDET + blockIdx.x * 1024 + tid];
    const unsigned int hi = (unsigned int)(key >> 32);
    const bool surv = (hi >= 0xBF000000u) && (((hi - 0xBF000000u) >> 15) >= T);

    const unsigned int bal = __ballot_sync(0xFFFFFFFFu, surv);
    const int lane = tid & 31;
    unsigned int base = 0;
    if (lane == 0 && bal) base = atomicAdd(&g_cnt[b], __popc(bal));
    base = __shfl_sync(0xFFFFFFFFu, base, 0);
    if (surv) {
        const unsigned int pos = base + __popc(bal & ((1u << lane) - 1u));
        if (pos < NCAND) g_cand[b * NCAND + pos] = key;
    }
}

// ================= K3: exact rank-sort + winner-only gather from input ==========
// grid (8, 32) x 256
__global__ void __launch_bounds__(256) rank_kernel(const float* __restrict__ in) {
    __shared__ unsigned long long sk[NCAND];
    const int b = blockIdx.y;
    const int i = blockIdx.x * 256 + threadIdx.x;

    for (int t = threadIdx.x; t < NCAND; t += 256)
        sk[t] = g_cand[b * NCAND + t];
    __syncthreads();

    unsigned int c = g_cnt[b];
    const int cnt = (c < NCAND) ? (int)c : NCAND;

    if (i >= cnt) {
        if (i < TOPK) {   // only reachable when cnt < TOPK: zero-fill row i
            float* o = g_srt + ((size_t)b * TOPK + i) * 8;
            *(float4*)(o)     = make_float4(0.f, 0.f, 0.f, 0.f);
            *(float4*)(o + 4) = make_float4(0.f, 0.f, 0.f, 0.f);
            g_box[(size_t)b * TOPK + i]  = make_float4(0.f, 0.f, 0.f, 0.f);
            g_area[(size_t)b * TOPK + i] = 0.f;
        }
        return;
    }

    const unsigned long long key = sk[i];
    int rank = 0, j = 0;
    for (; j + 4 <= cnt; j += 4)
        rank += (int)(sk[j] > key) + (int)(sk[j+1] > key)
              + (int)(sk[j+2] > key) + (int)(sk[j+3] > key);
    for (; j < cnt; ++j) rank += (int)(sk[j] > key);
    if (rank >= TOPK) return;

    const unsigned int n = 0xFFFFFFFFu - (unsigned int)(key & 0xFFFFFFFFull);
    const unsigned int r = n / 3u;
    const unsigned int a = n - r * 3u;
    const unsigned int s = ((r & 63u) << 6) | (r >> 6);

    const float* p = in + ((size_t)b * 255 + (size_t)a * 85) * NCELL + s;
    const float t0 = p[0 * NCELL];
    const float t1 = p[1 * NCELL];
    const float t2 = p[2 * NCELL];
    const float t3 = p[3 * NCELL];

    float best = p[5 * NCELL];
    int   bi   = 0;
    #pragma unroll 8
    for (int d = 1; d < NCLS; ++d) {
        const float v = p[(5 + d) * NCELL];
        if (v > best) { best = v; bi = d; }
    }

    const float conf  = __uint_as_float((unsigned int)(key >> 32) & 0x7FFFFFFFu);
    const float x_off = (float)((n >> 6) & 63);
    const float y_off = (float)(n & 63);
    const float cx = t0 + x_off, cy = t1 + y_off;
    const float hw = t2 * 0.5f,  hh = t3 * 0.5f;
    const float c0 = cx - hw, c1 = cy - hh, c2 = cx + hw, c3 = cy + hh;

    float* o = g_srt + ((size_t)b * TOPK + rank) * 8;
    *(float4*)(o)     = make_float4(c0, c1, c2, c3);
    *(float4*)(o + 4) = make_float4(conf, best, (float)bi, 0.f);

    const float sh = (float)bi * CLS_OFF;
    g_box[(size_t)b * TOPK + rank]  = make_float4(c0 + sh, c1 + sh, c2 + sh, c3 + sh);
    g_area[(size_t)b * TOPK + rank] = (c2 - c0) * (c3 - c1);
}

// ================= K4: IoU mask — upper-triangle pairs only =================
__global__ void __launch_bounds__(1024) mask_kernel() {
    __shared__ float4 sbox[TOPK];
    __shared__ float  sarea[TOPK];
    const int b = blockIdx.y;
    const int tid = threadIdx.x;

    sbox[tid]  = g_box[(size_t)b * TOPK + tid];
    sarea[tid] = g_area[(size_t)b * TOPK + tid];
    __syncthreads();

    const int p = blockIdx.x * 32 + (tid >> 5);   // pair index
    if (p >= NPAIRS) return;

    const float rt = sqrtf(4225.0f - 8.0f * (float)p);
    int qb = (int)((65.0f - rt) * 0.5f);
    if (tri_off(qb + 1) <= p) qb++;
    if (tri_off(qb) > p) qb--;
    const int w = qb + (p - tri_off(qb));
    const int q = (qb << 5) | (tid & 31);

    const float4 bx  = sbox[q];
    const float  myA = sarea[q];
    const int j0 = w << 5;

    unsigned int bits = 0;
    #pragma unroll 8
    for (int jj = 0; jj < 32; ++jj) {
        const int j = j0 + jj;
        const float4 ob = sbox[j];
        const float lx = fmaxf(bx.x, ob.x);
        const float ly = fmaxf(bx.y, ob.y);
        const float rx = fminf(bx.z, ob.z);
        const float ry = fminf(bx.w, ob.w);
        const float iw = fmaxf(rx - lx, 0.0f);
        const float ih = fmaxf(ry - ly, 0.0f);
        const float inter = iw * ih;
        const float denom = myA + sarea[j] - inter + 1e-9f;
        const bool hit = (denom > 0.0f) && (inter > IOU_THR * denom) && (j > q);
        if (hit) bits |= (1u << jj);
    }
    g_mask[((size_t)b * TOPK + q) * 32 + w] = bits;
}

// ================= K5: greedy + output + scratch cleanup =================
#define GREEDY_SMEM (TOPK * 32 * 4)   // 128 KB
__global__ void __launch_bounds__(1024) greedy_kernel(float* __restrict__ out) {
    extern __shared__ unsigned int smask[];
    __shared__ unsigned int svalid[32];
    __shared__ unsigned int skeepw[32];

    const int b = blockIdx.x, tid = threadIdx.x;

    const uint4* src = (const uint4*)(g_mask + (size_t)b * TOPK * 32);
    uint4* dst = (uint4*)smask;
    #pragma unroll
    for (int k = 0; k < 8; ++k) dst[tid + k * 1024] = src[tid + k * 1024];

    const float* o = g_srt + ((size_t)b * TOPK + tid) * 8;
    const float4 lo = *(const float4*)(o);
    const float4 hi = *(const float4*)(o + 4);
    const unsigned int bal = __ballot_sync(0xFFFFFFFFu, hi.x > CNF_THR);
    if ((tid & 31) == 0) svalid[tid >> 5] = bal;
    __syncthreads();

    if (tid < 32) {
        const int lane = tid;
        unsigned int sup = 0, keepw = 0;
        for (int blk = 0; blk < 32; ++blk) {
            const unsigned int ext = __shfl_sync(0xFFFFFFFFu, sup, blk);
            const unsigned int vv  = svalid[blk];

            unsigned int keepmask = 0;
            if (lane == 0) {
                unsigned int rr[32];
                #pragma unroll
                for (int i = 0; i < 32; ++i)
                    rr[i] = smask[(blk * 32 + i) * 32 + blk];
                unsigned int s = ext;
                #pragma unroll
                for (int i = 0; i < 32; ++i) {
                    if (!((s >> i) & 1u) && ((vv >> i) & 1u)) {
                        keepmask |= (1u << i);
                        s |= rr[i];
                    }
                }
            }
            keepmask = __shfl_sync(0xFFFFFFFFu, keepmask, 0);
            if (lane == blk) keepw = keepmask;

            if (lane >= blk) {
                #pragma unroll
                for (int i = 0; i < 32; ++i)
                    if ((keepmask >> i) & 1u) sup |= smask[(blk * 32 + i) * 32 + lane];
            }
        }
        skeepw[lane] = keepw;
    }
    __syncthreads();

    const bool kp = (skeepw[tid >> 5] >> (tid & 31)) & 1u;
    const float f = kp ? STRIDE_S : 0.0f;
    float* od = out + ((size_t)b * TOPK + tid) * 7;
    od[0] = f * lo.x; od[1] = f * lo.y; od[2] = f * lo.z; od[3] = f * lo.w;
    od[4] = f * hi.x; od[5] = f * hi.y; od[6] = f * hi.z;
    out[(size_t)B_IMGS * TOPK * 7 + (size_t)b * TOPK + tid] = kp ? 1.0f : 0.0f;

    // reset scratch for the next replay (invariant: zero at entry, zero at exit)
    if (tid < NBINS) g_hist[b * NBINS + tid] = 0u;
    if (tid == 0)    g_cnt[b] = 0u;
}

// ================= launcher =================
extern "C" void kernel_launch(void* const* d_in, const int* in_sizes, int n_in,
                              void* d_out, int out_size) {
    const float* in = (const float*)d_in[0];
    float* out = (float*)d_out;

    cudaFuncSetAttribute(greedy_kernel, cudaFuncAttributeMaxDynamicSharedMemorySize,
                         GREEDY_SMEM);

    conf_kernel<<<dim3(12, B_IMGS), 1024>>>(in);
    compact_kernel<<<dim3(12, B_IMGS), 1024>>>();
    rank_kernel<<<dim3(8, B_IMGS), 256>>>(in);
    mask_kernel<<<dim3((NPAIRS + 31) / 32, B_IMGS), 1024>>>();
    greedy_kernel<<<B_IMGS, 1024, GREEDY_SMEM>>>(out);
}

// round 10
// speedup vs baseline: 3.7659x; 1.0644x over previous
#include <cuda_runtime.h>
#include <cuda_bf16.h>
#include <cstdint>

#define B_IMGS   32
#define NCELL    4096
#define NDET     12288
#define NCLS     80
#define TOPK     1024
#define NCAND    2048
#define NBINS    256
#define CNF_THR  0.5f
#define IOU_THR  0.4f
#define CLS_OFF  10000.0f
#define STRIDE_S 8.0f
#define NPAIRS   528              // upper-triangle (qblock, word) pairs per image

// ---------------- device scratch ----------------
__device__ unsigned int        g_cnt[B_IMGS];
__device__ unsigned long long  g_cand[B_IMGS * NCAND];                 // 512 KB
__device__ float               g_srt[(size_t)B_IMGS * TOPK * 8];       // 1 MB
__device__ float4              g_box[(size_t)B_IMGS * TOPK];           // shifted boxes
__device__ float               g_area[(size_t)B_IMGS * TOPK];
__device__ unsigned int        g_mask[(size_t)B_IMGS * TOPK * 32];     // 4 MB (upper-tri only)

__device__ __forceinline__ unsigned int ord_f32(float f) {
    unsigned int u = __float_as_uint(f);
    return (u & 0x80000000u) ? ~u : (u | 0x80000000u);
}
__device__ __forceinline__ unsigned int inv_ord(unsigned int v) {
    return (v & 0x80000000u) ? (v & 0x7FFFFFFFu) : ~v;
}
__device__ __forceinline__ int tri_off(int qb) { return 32 * qb - (qb * (qb - 1)) / 2; }

// ================= K1: objectness keys (registers) + hist + threshold + compact =====
// 1 CTA per image, 1024 threads. Reads ONLY channel 4 (1.5 MB total).
__global__ void __launch_bounds__(1024) select_kernel(const float* __restrict__ in) {
    __shared__ unsigned int hist[NBINS];
    __shared__ unsigned int scnt;
    __shared__ unsigned int sT;

    const int b = blockIdx.x, tid = threadIdx.x;
    if (tid < NBINS) hist[tid] = 0u;
    if (tid == 0) scnt = 0u;
    __syncthreads();

    unsigned long long keys[12];
    #pragma unroll
    for (int k = 0; k < 12; ++k) {
        const int l = tid + k * 1024;          // 0..12287
        const int a = l >> 12;
        const int s = l & 4095;
        const float t4 = in[((size_t)b * 255 + (size_t)a * 85 + 4) * NCELL + s];
        const float conf = 1.0f / (1.0f + expf(-t4));
        const int n = (((s & 63) << 6) | (s >> 6)) * 3 + a;   // reference det order
        const float score = (conf > CNF_THR) ? conf : (-__int_as_float(0x7f800000));
        const unsigned int hi = ord_f32(score);
        keys[k] = ((unsigned long long)hi << 32)
                | (unsigned long long)(0xFFFFFFFFu - (unsigned int)n);
        if (hi >= 0xBF000000u) {
            unsigned int bin = (hi - 0xBF000000u) >> 15;
            if (bin > 255u) bin = 255u;
            atomicAdd(&hist[bin], 1u);
        }
    }
    __syncthreads();

    // warp 0: suffix-scan over 256 bins -> threshold bin T
    if (tid < 32) {
        const int lane = tid;
        unsigned int v[8];
        #pragma unroll
        for (int k = 0; k < 8; ++k) v[k] = hist[lane * 8 + k];
        unsigned int ls[9];
        ls[8] = 0u;
        #pragma unroll
        for (int k = 7; k >= 0; --k) ls[k] = ls[k + 1] + v[k];
        const unsigned int t = ls[0];
        unsigned int st = t;
        #pragma unroll
        for (int off = 1; off < 32; off <<= 1) {
            const unsigned int nn = __shfl_down_sync(0xFFFFFFFFu, st, off);
            if (lane + off < 32) st += nn;
        }
        const unsigned int after = st - t;   // suffix over lanes > lane
        if (lane == 0) sT = 0u;
        __syncwarp();
        #pragma unroll
        for (int k = 0; k < 8; ++k) {
            const unsigned int sfx = ls[k] + after;
            const unsigned int nxt = ls[k + 1] + after;
            if (sfx >= TOPK && nxt < TOPK) sT = (unsigned int)(lane * 8 + k);
        }
    }
    __syncthreads();
    const unsigned int T = sT;
    const int lane = tid & 31;

    #pragma unroll
    for (int k = 0; k < 12; ++k) {
        const unsigned int hi = (unsigned int)(keys[k] >> 32);
        const bool surv = (hi >= 0xBF000000u) && (((hi - 0xBF000000u) >> 15) >= T);
        const unsigned int bal = __ballot_sync(0xFFFFFFFFu, surv);
        unsigned int base = 0;
        if (lane == 0 && bal) base = atomicAdd(&scnt, __popc(bal));
        base = __shfl_sync(0xFFFFFFFFu, base, 0);
        if (surv) {
            const unsigned int pos = base + __popc(bal & ((1u << lane) - 1u));
            if (pos < NCAND) g_cand[b * NCAND + pos] = keys[k];
        }
    }
    __syncthreads();
    if (tid == 0) g_cnt[b] = (scnt < NCAND) ? scnt : NCAND;
}

// ================= K2: warp-per-candidate rank + winner gather ==================
// grid (64, 32) x 1024 = 32 warps/CTA, 2048 warps/image.
__global__ void __launch_bounds__(1024) rank_kernel(const float* __restrict__ in) {
    __shared__ unsigned long long sk[NCAND];   // 16 KB
    const int b = blockIdx.y, tid = threadIdx.x;

    for (int t = tid; t < NCAND; t += 1024)
        sk[t] = g_cand[b * NCAND + t];
    __syncthreads();

    const unsigned int cr = g_cnt[b];
    const int cnt = (cr < NCAND) ? (int)cr : NCAND;

    const int wid  = tid >> 5;
    const int lane = tid & 31;
    const int c    = blockIdx.x * 32 + wid;    // candidate slot

    if (c >= cnt) {
        if (c < TOPK && lane == 0) {           // only when cnt < TOPK
            float* o = g_srt + ((size_t)b * TOPK + c) * 8;
            *(float4*)(o)     = make_float4(0.f, 0.f, 0.f, 0.f);
            *(float4*)(o + 4) = make_float4(0.f, 0.f, 0.f, 0.f);
            g_box[(size_t)b * TOPK + c]  = make_float4(0.f, 0.f, 0.f, 0.f);
            g_area[(size_t)b * TOPK + c] = 0.f;
        }
        return;
    }

    const unsigned long long key = sk[c];

    // exact rank: count keys greater than mine (all distinct)
    int rk = 0;
    for (int j = lane; j < cnt; j += 32) rk += (int)(sk[j] > key);
    #pragma unroll
    for (int off = 16; off > 0; off >>= 1)
        rk += __shfl_down_sync(0xFFFFFFFFu, rk, off);
    rk = __shfl_sync(0xFFFFFFFFu, rk, 0);
    if (rk >= TOPK) return;

    const unsigned int n = 0xFFFFFFFFu - (unsigned int)(key & 0xFFFFFFFFull);
    const unsigned int r = n / 3u;
    const unsigned int a = n - r * 3u;
    const unsigned int s = ((r & 63u) << 6) | (r >> 6);
    const float* p = in + ((size_t)b * 255 + (size_t)a * 85) * NCELL + s;

    // lane-parallel class argmax, first-occurrence tie-break via (ord<<32)|(255-d)
    unsigned long long best;
    {
        const float v0 = p[(5 + lane) * NCELL];
        best = ((unsigned long long)ord_f32(v0) << 32) | (unsigned long long)(255 - lane);
        const float v1 = p[(5 + lane + 32) * NCELL];
        const unsigned long long p1 =
            ((unsigned long long)ord_f32(v1) << 32) | (unsigned long long)(255 - (lane + 32));
        if (p1 > best) best = p1;
        if (lane < 16) {
            const float v2 = p[(5 + lane + 64) * NCELL];
            const unsigned long long p2 =
                ((unsigned long long)ord_f32(v2) << 32) | (unsigned long long)(255 - (lane + 64));
            if (p2 > best) best = p2;
        }
        #pragma unroll
        for (int off = 16; off > 0; off >>= 1) {
            const unsigned long long ot = __shfl_down_sync(0xFFFFFFFFu, best, off);
            if (ot > best) best = ot;
        }
    }

    if (lane == 0) {
        const float t0 = p[0 * NCELL];
        const float t1 = p[1 * NCELL];
        const float t2 = p[2 * NCELL];
        const float t3 = p[3 * NCELL];

        const float conf  = __uint_as_float((unsigned int)(key >> 32) & 0x7FFFFFFFu);
        const float x_off = (float)((n >> 6) & 63);
        const float y_off = (float)(n & 63);
        const float cx = t0 + x_off, cy = t1 + y_off;
        const float hw = t2 * 0.5f,  hh = t3 * 0.5f;
        const float c0 = cx - hw, c1 = cy - hh, c2 = cx + hw, c3 = cy + hh;

        const int   bi = 255 - (int)(best & 0xFFull);
        const float bv = __uint_as_float(inv_ord((unsigned int)(best >> 32)));

        float* o = g_srt + ((size_t)b * TOPK + rk) * 8;
        *(float4*)(o)     = make_float4(c0, c1, c2, c3);
        *(float4*)(o + 4) = make_float4(conf, bv, (float)bi, 0.f);

        const float sh = (float)bi * CLS_OFF;
        g_box[(size_t)b * TOPK + rk]  = make_float4(c0 + sh, c1 + sh, c2 + sh, c3 + sh);
        g_area[(size_t)b * TOPK + rk] = (c2 - c0) * (c3 - c1);
    }
}

// ================= K3: IoU mask — upper-triangle pairs only =================
__global__ void __launch_bounds__(1024) mask_kernel() {
    __shared__ float4 sbox[TOPK];
    __shared__ float  sarea[TOPK];
    const int b = blockIdx.y;
    const int tid = threadIdx.x;

    sbox[tid]  = g_box[(size_t)b * TOPK + tid];
    sarea[tid] = g_area[(size_t)b * TOPK + tid];
    __syncthreads();

    const int p = blockIdx.x * 32 + (tid >> 5);   // pair index
    if (p >= NPAIRS) return;

    const float rt = sqrtf(4225.0f - 8.0f * (float)p);
    int qb = (int)((65.0f - rt) * 0.5f);
    if (tri_off(qb + 1) <= p) qb++;
    if (tri_off(qb) > p) qb--;
    const int w = qb + (p - tri_off(qb));
    const int lane = tid & 31;
    const int q = (qb << 5) | lane;

    const float4 bx   = sbox[q];
    const float  myAe = sarea[q] + 1e-9f;
    const int j0 = w << 5;

    unsigned int bits = 0;
    #pragma unroll 8
    for (int jj = 0; jj < 32; ++jj) {
        const int j = j0 + jj;
        const float4 ob = sbox[j];
        const float lx = fmaxf(bx.x, ob.x);
        const float ly = fmaxf(bx.y, ob.y);
        const float rx = fminf(bx.z, ob.z);
        const float ry = fminf(bx.w, ob.w);
        const float iw = fmaxf(rx - lx, 0.0f);
        const float ih = fmaxf(ry - ly, 0.0f);
        const float inter = iw * ih;
        const float denom = myAe + sarea[j] - inter;
        const bool hit = (denom > 0.0f) && (inter > IOU_THR * denom);
        if (hit) bits |= (1u << jj);
    }
    // diagonal word: clear bits jj <= lane (only j > q may suppress)
    if (w == qb) bits &= ~((2u << lane) - 1u);
    g_mask[((size_t)b * TOPK + q) * 32 + w] = bits;
}

// ================= K4: greedy + output =================
#define GREEDY_SMEM (TOPK * 32 * 4)   // 128 KB
__global__ void __launch_bounds__(1024) greedy_kernel(float* __restrict__ out) {
    extern __shared__ unsigned int smask[];
    __shared__ unsigned int svalid[32];
    __shared__ unsigned int skeepw[32];

    const int b = blockIdx.x, tid = threadIdx.x;

    const uint4* src = (const uint4*)(g_mask + (size_t)b * TOPK * 32);
    uint4* dst = (uint4*)smask;
    #pragma unroll
    for (int k = 0; k < 8; ++k) dst[tid + k * 1024] = src[tid + k * 1024];

    const float* o = g_srt + ((size_t)b * TOPK + tid) * 8;
    const float4 lo = *(const float4*)(o);
    const float4 hi = *(const float4*)(o + 4);
    const unsigned int bal = __ballot_sync(0xFFFFFFFFu, hi.x > CNF_THR);
    if ((tid & 31) == 0) svalid[tid >> 5] = bal;
    __syncthreads();

    if (tid < 32) {
        const int lane = tid;
        unsigned int sup = 0, keepw = 0;
        for (int blk = 0; blk < 32; ++blk) {
            const unsigned int ext = __shfl_sync(0xFFFFFFFFu, sup, blk);
            const unsigned int vv  = svalid[blk];

            unsigned int keepmask = 0;
            if (lane == 0) {
                unsigned int rr[32];
                #pragma unroll
                for (int i = 0; i < 32; ++i)
                    rr[i] = smask[(blk * 32 + i) * 32 + blk];
                unsigned int s = ext;
                #pragma unroll
                for (int i = 0; i < 32; ++i) {
                    if (!((s >> i) & 1u) && ((vv >> i) & 1u)) {
                        keepmask |= (1u << i);
                        s |= rr[i];
                    }
                }
            }
            keepmask = __shfl_sync(0xFFFFFFFFu, keepmask, 0);
            if (lane == blk) keepw = keepmask;

            if (lane >= blk) {   // lower-triangle words never written -> skip
                #pragma unroll
                for (int i = 0; i < 32; ++i)
                    if ((keepmask >> i) & 1u) sup |= smask[(blk * 32 + i) * 32 + lane];
            }
        }
        skeepw[lane] = keepw;
    }
    __syncthreads();

    const bool kp = (skeepw[tid >> 5] >> (tid & 31)) & 1u;
    const float f = kp ? STRIDE_S : 0.0f;
    float* od = out + ((size_t)b * TOPK + tid) * 7;
    od[0] = f * lo.x; od[1] = f * lo.y; od[2] = f * lo.z; od[3] = f * lo.w;
    od[4] = f * hi.x; od[5] = f * hi.y; od[6] = f * hi.z;
    out[(size_t)B_IMGS * TOPK * 7 + (size_t)b * TOPK + tid] = kp ? 1.0f : 0.0f;
}

// ================= launcher =================
extern "C" void kernel_launch(void* const* d_in, const int* in_sizes, int n_in,
                              void* d_out, int out_size) {
    const float* in = (const float*)d_in[0];
    float* out = (float*)d_out;

    cudaFuncSetAttribute(greedy_kernel, cudaFuncAttributeMaxDynamicSharedMemorySize,
                         GREEDY_SMEM);

    select_kernel<<<B_IMGS, 1024>>>(in);
    rank_kernel<<<dim3(64, B_IMGS), 1024>>>(in);
    mask_kernel<<<dim3((NPAIRS + 31) / 32, B_IMGS), 1024>>>();
    greedy_kernel<<<B_IMGS, 1024, GREEDY_SMEM>>>(out);
}

// round 12
// speedup vs baseline: 3.9495x; 1.0488x over previous
#include <cuda_runtime.h>
#include <cuda_bf16.h>
#include <cstdint>

#define B_IMGS   32
#define NCELL    4096
#define NDET     12288
#define NCLS     80
#define TOPK     1024
#define NCAND    2048
#define NBINS    256
#define CNF_THR  0.5f
#define IOU_THR  0.4f
#define CLS_OFF  10000.0f
#define STRIDE_S 8.0f
#define NPAIRS   528              // upper-triangle (qblock, word) pairs per image

// ---------------- device scratch ----------------
__device__ unsigned int        g_cnt[B_IMGS];
__device__ unsigned long long  g_cand[B_IMGS * NCAND];                 // 512 KB
__device__ float               g_srt[(size_t)B_IMGS * TOPK * 8];       // 1 MB
__device__ float4              g_box[(size_t)B_IMGS * TOPK];           // shifted boxes
__device__ float               g_area[(size_t)B_IMGS * TOPK];
__device__ unsigned int        g_mask[(size_t)B_IMGS * TOPK * 32];     // upper-tri written; lower-tri stays 0

__device__ __forceinline__ unsigned int ord_f32(float f) {
    unsigned int u = __float_as_uint(f);
    return (u & 0x80000000u) ? ~u : (u | 0x80000000u);
}
__device__ __forceinline__ unsigned int inv_ord(unsigned int v) {
    return (v & 0x80000000u) ? (v & 0x7FFFFFFFu) : ~v;
}
__device__ __forceinline__ int tri_off(int qb) { return 32 * qb - (qb * (qb - 1)) / 2; }

// ================= K1: objectness keys + hist + threshold + compact =================
// 1 CTA per image, 1024 threads. Reads ONLY channel 4 (1.5 MB total).
__global__ void __launch_bounds__(1024) select_kernel(const float* __restrict__ in) {
    __shared__ unsigned int hist[NBINS];
    __shared__ unsigned int scnt;
    __shared__ unsigned int sT;

    const int b = blockIdx.x, tid = threadIdx.x;
    if (tid < NBINS) hist[tid] = 0u;
    if (tid == 0) scnt = 0u;
    __syncthreads();

    unsigned long long keys[12];
    #pragma unroll
    for (int k = 0; k < 12; ++k) {
        const int l = tid + k * 1024;          // 0..12287
        const int a = l >> 12;
        const int s = l & 4095;
        const float t4 = in[((size_t)b * 255 + (size_t)a * 85 + 4) * NCELL + s];
        const float conf = 1.0f / (1.0f + expf(-t4));
        const int n = (((s & 63) << 6) | (s >> 6)) * 3 + a;   // reference det order
        const float score = (conf > CNF_THR) ? conf : (-__int_as_float(0x7f800000));
        const unsigned int hi = ord_f32(score);
        keys[k] = ((unsigned long long)hi << 32)
                | (unsigned long long)(0xFFFFFFFFu - (unsigned int)n);
        if (hi >= 0xBF000000u) {
            unsigned int bin = (hi - 0xBF000000u) >> 15;
            if (bin > 255u) bin = 255u;
            atomicAdd(&hist[bin], 1u);
        }
    }
    __syncthreads();

    // warp 0: suffix-scan over 256 bins -> threshold bin T
    if (tid < 32) {
        const int lane = tid;
        unsigned int v[8];
        #pragma unroll
        for (int k = 0; k < 8; ++k) v[k] = hist[lane * 8 + k];
        unsigned int ls[9];
        ls[8] = 0u;
        #pragma unroll
        for (int k = 7; k >= 0; --k) ls[k] = ls[k + 1] + v[k];
        const unsigned int t = ls[0];
        unsigned int st = t;
        #pragma unroll
        for (int off = 1; off < 32; off <<= 1) {
            const unsigned int nn = __shfl_down_sync(0xFFFFFFFFu, st, off);
            if (lane + off < 32) st += nn;
        }
        const unsigned int after = st - t;   // suffix over lanes > lane
        if (lane == 0) sT = 0u;
        __syncwarp();
        #pragma unroll
        for (int k = 0; k < 8; ++k) {
            const unsigned int sfx = ls[k] + after;
            const unsigned int nxt = ls[k + 1] + after;
            if (sfx >= TOPK && nxt < TOPK) sT = (unsigned int)(lane * 8 + k);
        }
    }
    __syncthreads();
    const unsigned int T = sT;
    const int lane = tid & 31;

    #pragma unroll
    for (int k = 0; k < 12; ++k) {
        const unsigned int hi = (unsigned int)(keys[k] >> 32);
        const bool surv = (hi >= 0xBF000000u) && (((hi - 0xBF000000u) >> 15) >= T);
        const unsigned int bal = __ballot_sync(0xFFFFFFFFu, surv);
        unsigned int base = 0;
        if (lane == 0 && bal) base = atomicAdd(&scnt, __popc(bal));
        base = __shfl_sync(0xFFFFFFFFu, base, 0);
        if (surv) {
            const unsigned int pos = base + __popc(bal & ((1u << lane) - 1u));
            if (pos < NCAND) g_cand[b * NCAND + pos] = keys[k];
        }
    }
    __syncthreads();
    if (tid == 0) g_cnt[b] = (scnt < NCAND) ? scnt : NCAND;
}

// ================= K2: warp-per-candidate rank + winner gather ==================
// grid (64, 32) x 1024 = 32 warps/CTA.
__global__ void __launch_bounds__(1024) rank_kernel(const float* __restrict__ in) {
    __shared__ unsigned long long sk[NCAND];   // 16 KB
    const int b = blockIdx.y, tid = threadIdx.x;

    const unsigned int cr = g_cnt[b];
    const int cnt = (cr < NCAND) ? (int)cr : NCAND;

    const int wid  = tid >> 5;
    const int lane = tid & 31;
    const int c    = blockIdx.x * 32 + wid;    // candidate slot

    // whole-CTA early exit: no rank work -> no staging needed (uniform per CTA)
    if (blockIdx.x * 32 >= cnt) {
        if (c >= cnt && c < TOPK && lane == 0) {   // only when cnt < TOPK
            float* o = g_srt + ((size_t)b * TOPK + c) * 8;
            *(float4*)(o)     = make_float4(0.f, 0.f, 0.f, 0.f);
            *(float4*)(o + 4) = make_float4(0.f, 0.f, 0.f, 0.f);
            g_box[(size_t)b * TOPK + c]  = make_float4(0.f, 0.f, 0.f, 0.f);
            g_area[(size_t)b * TOPK + c] = 0.f;
        }
        return;
    }

    for (int t = tid; t < NCAND; t += 1024)
        sk[t] = g_cand[b * NCAND + t];
    __syncthreads();

    if (c >= cnt) {
        if (c < TOPK && lane == 0) {           // only when cnt < TOPK
            float* o = g_srt + ((size_t)b * TOPK + c) * 8;
            *(float4*)(o)     = make_float4(0.f, 0.f, 0.f, 0.f);
            *(float4*)(o + 4) = make_float4(0.f, 0.f, 0.f, 0.f);
            g_box[(size_t)b * TOPK + c]  = make_float4(0.f, 0.f, 0.f, 0.f);
            g_area[(size_t)b * TOPK + c] = 0.f;
        }
        return;
    }

    const unsigned long long key = sk[c];

    // exact rank: count keys greater than mine (all distinct)
    int rk = 0;
    for (int j = lane; j < cnt; j += 32) rk += (int)(sk[j] > key);
    #pragma unroll
    for (int off = 16; off > 0; off >>= 1)
        rk += __shfl_down_sync(0xFFFFFFFFu, rk, off);
    rk = __shfl_sync(0xFFFFFFFFu, rk, 0);
    if (rk >= TOPK) return;

    const unsigned int n = 0xFFFFFFFFu - (unsigned int)(key & 0xFFFFFFFFull);
    const unsigned int r = n / 3u;
    const unsigned int a = n - r * 3u;
    const unsigned int s = ((r & 63u) << 6) | (r >> 6);
    const float* p = in + ((size_t)b * 255 + (size_t)a * 85) * NCELL + s;

    // lane-parallel class argmax, first-occurrence tie-break via (ord<<32)|(255-d)
    unsigned long long best;
    {
        const float v0 = p[(5 + lane) * NCELL];
        best = ((unsigned long long)ord_f32(v0) << 32) | (unsigned long long)(255 - lane);
        const float v1 = p[(5 + lane + 32) * NCELL];
        const unsigned long long p1 =
            ((unsigned long long)ord_f32(v1) << 32) | (unsigned long long)(255 - (lane + 32));
        if (p1 > best) best = p1;
        if (lane < 16) {
            const float v2 = p[(5 + lane + 64) * NCELL];
            const unsigned long long p2 =
                ((unsigned long long)ord_f32(v2) << 32) | (unsigned long long)(255 - (lane + 64));
            if (p2 > best) best = p2;
        }
        #pragma unroll
        for (int off = 16; off > 0; off >>= 1) {
            const unsigned long long ot = __shfl_down_sync(0xFFFFFFFFu, best, off);
            if (ot > best) best = ot;
        }
    }

    if (lane == 0) {
        const float t0 = p[0 * NCELL];
        const float t1 = p[1 * NCELL];
        const float t2 = p[2 * NCELL];
        const float t3 = p[3 * NCELL];

        const float conf  = __uint_as_float((unsigned int)(key >> 32) & 0x7FFFFFFFu);
        const float x_off = (float)((n >> 6) & 63);
        const float y_off = (float)(n & 63);
        const float cx = t0 + x_off, cy = t1 + y_off;
        const float hw = t2 * 0.5f,  hh = t3 * 0.5f;
        const float c0 = cx - hw, c1 = cy - hh, c2 = cx + hw, c3 = cy + hh;

        const int   bi = 255 - (int)(best & 0xFFull);
        const float bv = __uint_as_float(inv_ord((unsigned int)(best >> 32)));

        float* o = g_srt + ((size_t)b * TOPK + rk) * 8;
        *(float4*)(o)     = make_float4(c0, c1, c2, c3);
        *(float4*)(o + 4) = make_float4(conf, bv, (float)bi, 0.f);

        const float sh = (float)bi * CLS_OFF;
        g_box[(size_t)b * TOPK + rk]  = make_float4(c0 + sh, c1 + sh, c2 + sh, c3 + sh);
        g_area[(size_t)b * TOPK + rk] = (c2 - c0) * (c3 - c1);
    }
}

// ================= K3: IoU mask — upper-triangle pairs only =================
__global__ void __launch_bounds__(1024) mask_kernel() {
    __shared__ float4 sbox[TOPK];
    __shared__ float  sarea[TOPK];
    const int b = blockIdx.y;
    const int tid = threadIdx.x;

    sbox[tid]  = g_box[(size_t)b * TOPK + tid];
    sarea[tid] = g_area[(size_t)b * TOPK + tid];
    __syncthreads();

    const int p = blockIdx.x * 32 + (tid >> 5);   // pair index
    if (p >= NPAIRS) return;

    const float rt = sqrtf(4225.0f - 8.0f * (float)p);
    int qb = (int)((65.0f - rt) * 0.5f);
    if (tri_off(qb + 1) <= p) qb++;
    if (tri_off(qb) > p) qb--;
    const int w = qb + (p - tri_off(qb));
    const int lane = tid & 31;
    const int q = (qb << 5) | lane;

    const float4 bx   = sbox[q];
    const float  myAe = sarea[q] + 1e-9f;
    const int j0 = w << 5;

    unsigned int bits = 0;
    #pragma unroll 8
    for (int jj = 0; jj < 32; ++jj) {
        const int j = j0 + jj;
        const float4 ob = sbox[j];
        const float lx = fmaxf(bx.x, ob.x);
        const float ly = fmaxf(bx.y, ob.y);
        const float rx = fminf(bx.z, ob.z);
        const float ry = fminf(bx.w, ob.w);
        const float iw = fmaxf(rx - lx, 0.0f);
        const float ih = fmaxf(ry - ly, 0.0f);
        const float inter = iw * ih;
        const float denom = myAe + sarea[j] - inter;
        const bool hit = (denom > 0.0f) && (inter > IOU_THR * denom);
        if (hit) bits |= (1u << jj);
    }
    // diagonal word: clear bits jj <= lane (only j > q may suppress)
    if (w == qb) bits &= ~((2u << lane) - 1u);
    g_mask[((size_t)b * TOPK + q) * 32 + w] = bits;
}

// ================= K4: greedy (branch-free serial) + output =================
#define GREEDY_SMEM (TOPK * 32 * 4)   // 128 KB
__global__ void __launch_bounds__(1024) greedy_kernel(float* __restrict__ out) {
    extern __shared__ unsigned int smask[];
    __shared__ unsigned int svalid[32];
    __shared__ unsigned int skeepw[32];

    const int b = blockIdx.x, tid = threadIdx.x;

    const uint4* src = (const uint4*)(g_mask + (size_t)b * TOPK * 32);
    uint4* dst = (uint4*)smask;
    #pragma unroll
    for (int k = 0; k < 8; ++k) dst[tid + k * 1024] = src[tid + k * 1024];

    const float* o = g_srt + ((size_t)b * TOPK + tid) * 8;
    const float4 lo = *(const float4*)(o);
    const float4 hi = *(const float4*)(o + 4);
    const unsigned int bal = __ballot_sync(0xFFFFFFFFu, hi.x > CNF_THR);
    if ((tid & 31) == 0) svalid[tid >> 5] = bal;
    __syncthreads();

    if (tid < 32) {
        const int lane = tid;
        unsigned int sup = 0, keepw = 0;
        for (int blk = 0; blk < 32; ++blk) {
            const unsigned int ext = __shfl_sync(0xFFFFFFFFu, sup, blk);
            const unsigned int vv  = svalid[blk];

            unsigned int keepmask = 0;
            if (lane == 0) {
                unsigned int rr[32];
                #pragma unroll
                for (int i = 0; i < 32; ++i)
                    rr[i] = smask[(blk * 32 + i) * 32 + blk];
                unsigned int s = ext;
                #pragma unroll
                for (int i = 0; i < 32; ++i) {     // branch-free greedy step
                    const unsigned int kb = ((~s >> i) & (vv >> i)) & 1u;
                    keepmask |= kb << i;
                    s |= rr[i] & (0u - kb);
                }
            }
            keepmask = __shfl_sync(0xFFFFFFFFu, keepmask, 0);
            if (lane == blk) keepw = keepmask;

            // branch-free OR-apply; lower-triangle words are 0, contribute nothing
            #pragma unroll
            for (int i = 0; i < 32; ++i)
                sup |= smask[(blk * 32 + i) * 32 + lane] & (0u - ((keepmask >> i) & 1u));
        }
        skeepw[lane] = keepw;
    }
    __syncthreads();

    const bool kp = (skeepw[tid >> 5] >> (tid & 31)) & 1u;
    const float f = kp ? STRIDE_S : 0.0f;
    float* od = out + ((size_t)b * TOPK + tid) * 7;
    od[0] = f * lo.x; od[1] = f * lo.y; od[2] = f * lo.z; od[3] = f * lo.w;
    od[4] = f * hi.x; od[5] = f * hi.y; od[6] = f * hi.z;
    out[(size_t)B_IMGS * TOPK * 7 + (size_t)b * TOPK + tid] = kp ? 1.0f : 0.0f;
}

// ================= launcher =================
extern "C" void kernel_launch(void* const* d_in, const int* in_sizes, int n_in,
                              void* d_out, int out_size) {
    const float* in = (const float*)d_in[0];
    float* out = (float*)d_out;

    cudaFuncSetAttribute(greedy_kernel, cudaFuncAttributeMaxDynamicSharedMemorySize,
                         GREEDY_SMEM);

    select_kernel<<<B_IMGS, 1024>>>(in);
    rank_kernel<<<dim3(64, B_IMGS), 1024>>>(in);
    mask_kernel<<<dim3((NPAIRS + 31) / 32, B_IMGS), 1024>>>();
    greedy_kernel<<<B_IMGS, 1024, GREEDY_SMEM>>>(out);
}

// round 16
// speedup vs baseline: 4.7632x; 1.2060x over previous
#include <cuda_runtime.h>
#include <cuda_bf16.h>
#include <cstdint>

#define B_IMGS   32
#define NCELL    4096
#define NDET     12288
#define NCLS     80
#define TOPK     1024
#define NCAND    2048
#define NBINS    256
#define CNF_THR  0.5f
#define IOU_THR  0.4f
#define CLS_OFF  10000.0f
#define STRIDE_S 8.0f
#define NPAIRS   528              // upper-triangle (qblock, word) pairs per image

// ---------------- device scratch ----------------
__device__ unsigned int        g_cnt[B_IMGS];
__device__ unsigned long long  g_cand[B_IMGS * NCAND];                 // 512 KB
__device__ float               g_srt[(size_t)B_IMGS * TOPK * 8];       // 1 MB
__device__ float4              g_box[(size_t)B_IMGS * TOPK];           // shifted boxes
__device__ float               g_area[(size_t)B_IMGS * TOPK];
__device__ unsigned int        g_mask[(size_t)B_IMGS * TOPK * 32];     // upper-tri written; lower-tri stays 0
__device__ unsigned int        g_any[B_IMGS * 32];                     // rowblock nonzero summary (reset by greedy)

__device__ __forceinline__ unsigned int ord_f32(float f) {
    unsigned int u = __float_as_uint(f);
    return (u & 0x80000000u) ? ~u : (u | 0x80000000u);
}
__device__ __forceinline__ unsigned int inv_ord(unsigned int v) {
    return (v & 0x80000000u) ? (v & 0x7FFFFFFFu) : ~v;
}
__device__ __forceinline__ int tri_off(int qb) { return 32 * qb - (qb * (qb - 1)) / 2; }

// ================= K1: objectness keys + hist + threshold + compact =================
// 1 CTA per image, 1024 threads. Reads ONLY channel 4 (1.5 MB total).
__global__ void __launch_bounds__(1024) select_kernel(const float* __restrict__ in) {
    __shared__ unsigned int hist[NBINS];
    __shared__ unsigned int scnt;
    __shared__ unsigned int sT;

    const int b = blockIdx.x, tid = threadIdx.x;
    if (tid < NBINS) hist[tid] = 0u;
    if (tid == 0) scnt = 0u;
    __syncthreads();

    unsigned long long keys[12];
    #pragma unroll
    for (int k = 0; k < 12; ++k) {
        const int l = tid + k * 1024;          // 0..12287
        const int a = l >> 12;
        const int s = l & 4095;
        const float t4 = in[((size_t)b * 255 + (size_t)a * 85 + 4) * NCELL + s];
        const float conf = 1.0f / (1.0f + expf(-t4));
        const int n = (((s & 63) << 6) | (s >> 6)) * 3 + a;   // reference det order
        const float score = (conf > CNF_THR) ? conf : (-__int_as_float(0x7f800000));
        const unsigned int hi = ord_f32(score);
        keys[k] = ((unsigned long long)hi << 32)
                | (unsigned long long)(0xFFFFFFFFu - (unsigned int)n);
        if (hi >= 0xBF000000u) {
            unsigned int bin = (hi - 0xBF000000u) >> 15;
            if (bin > 255u) bin = 255u;
            atomicAdd(&hist[bin], 1u);
        }
    }
    __syncthreads();

    // warp 0: suffix-scan over 256 bins -> threshold bin T
    if (tid < 32) {
        const int lane = tid;
        unsigned int v[8];
        #pragma unroll
        for (int k = 0; k < 8; ++k) v[k] = hist[lane * 8 + k];
        unsigned int ls[9];
        ls[8] = 0u;
        #pragma unroll
        for (int k = 7; k >= 0; --k) ls[k] = ls[k + 1] + v[k];
        const unsigned int t = ls[0];
        unsigned int st = t;
        #pragma unroll
        for (int off = 1; off < 32; off <<= 1) {
            const unsigned int nn = __shfl_down_sync(0xFFFFFFFFu, st, off);
            if (lane + off < 32) st += nn;
        }
        const unsigned int after = st - t;   // suffix over lanes > lane
        if (lane == 0) sT = 0u;
        __syncwarp();
        #pragma unroll
        for (int k = 0; k < 8; ++k) {
            const unsigned int sfx = ls[k] + after;
            const unsigned int nxt = ls[k + 1] + after;
            if (sfx >= TOPK && nxt < TOPK) sT = (unsigned int)(lane * 8 + k);
        }
    }
    __syncthreads();
    const unsigned int T = sT;
    const int lane = tid & 31;

    #pragma unroll
    for (int k = 0; k < 12; ++k) {
        const unsigned int hi = (unsigned int)(keys[k] >> 32);
        const bool surv = (hi >= 0xBF000000u) && (((hi - 0xBF000000u) >> 15) >= T);
        const unsigned int bal = __ballot_sync(0xFFFFFFFFu, surv);
        unsigned int base = 0;
        if (lane == 0 && bal) base = atomicAdd(&scnt, __popc(bal));
        base = __shfl_sync(0xFFFFFFFFu, base, 0);
        if (surv) {
            const unsigned int pos = base + __popc(bal & ((1u << lane) - 1u));
            if (pos < NCAND) g_cand[b * NCAND + pos] = keys[k];
        }
    }
    __syncthreads();
    if (tid == 0) g_cnt[b] = (scnt < NCAND) ? scnt : NCAND;
}

// ================= K2: warp-per-candidate rank + winner gather ==================
// grid (64, 32) x 1024 = 32 warps/CTA.
__global__ void __launch_bounds__(1024) rank_kernel(const float* __restrict__ in) {
    __shared__ unsigned long long sk[NCAND];   // 16 KB
    const int b = blockIdx.y, tid = threadIdx.x;

    const unsigned int cr = g_cnt[b];
    const int cnt = (cr < NCAND) ? (int)cr : NCAND;

    const int wid  = tid >> 5;
    const int lane = tid & 31;
    const int c    = blockIdx.x * 32 + wid;    // candidate slot

    // whole-CTA early exit: no rank work -> no staging needed (uniform per CTA)
    if (blockIdx.x * 32 >= cnt) {
        if (c >= cnt && c < TOPK && lane == 0) {   // only when cnt < TOPK
            float* o = g_srt + ((size_t)b * TOPK + c) * 8;
            *(float4*)(o)     = make_float4(0.f, 0.f, 0.f, 0.f);
            *(float4*)(o + 4) = make_float4(0.f, 0.f, 0.f, 0.f);
            g_box[(size_t)b * TOPK + c]  = make_float4(0.f, 0.f, 0.f, 0.f);
            g_area[(size_t)b * TOPK + c] = 0.f;
        }
        return;
    }

    for (int t = tid; t < NCAND; t += 1024)
        sk[t] = g_cand[b * NCAND + t];
    __syncthreads();

    if (c >= cnt) {
        if (c < TOPK && lane == 0) {           // only when cnt < TOPK
            float* o = g_srt + ((size_t)b * TOPK + c) * 8;
            *(float4*)(o)     = make_float4(0.f, 0.f, 0.f, 0.f);
            *(float4*)(o + 4) = make_float4(0.f, 0.f, 0.f, 0.f);
            g_box[(size_t)b * TOPK + c]  = make_float4(0.f, 0.f, 0.f, 0.f);
            g_area[(size_t)b * TOPK + c] = 0.f;
        }
        return;
    }

    const unsigned long long key = sk[c];

    // exact rank: count keys greater than mine (all distinct)
    int rk = 0;
    for (int j = lane; j < cnt; j += 32) rk += (int)(sk[j] > key);
    #pragma unroll
    for (int off = 16; off > 0; off >>= 1)
        rk += __shfl_down_sync(0xFFFFFFFFu, rk, off);
    rk = __shfl_sync(0xFFFFFFFFu, rk, 0);
    if (rk >= TOPK) return;

    const unsigned int n = 0xFFFFFFFFu - (unsigned int)(key & 0xFFFFFFFFull);
    const unsigned int r = n / 3u;
    const unsigned int a = n - r * 3u;
    const unsigned int s = ((r & 63u) << 6) | (r >> 6);
    const float* p = in + ((size_t)b * 255 + (size_t)a * 85) * NCELL + s;

    // lane-parallel class argmax, first-occurrence tie-break via (ord<<32)|(255-d)
    unsigned long long best;
    {
        const float v0 = p[(5 + lane) * NCELL];
        best = ((unsigned long long)ord_f32(v0) << 32) | (unsigned long long)(255 - lane);
        const float v1 = p[(5 + lane + 32) * NCELL];
        const unsigned long long p1 =
            ((unsigned long long)ord_f32(v1) << 32) | (unsigned long long)(255 - (lane + 32));
        if (p1 > best) best = p1;
        if (lane < 16) {
            const float v2 = p[(5 + lane + 64) * NCELL];
            const unsigned long long p2 =
                ((unsigned long long)ord_f32(v2) << 32) | (unsigned long long)(255 - (lane + 64));
            if (p2 > best) best = p2;
        }
        #pragma unroll
        for (int off = 16; off > 0; off >>= 1) {
            const unsigned long long ot = __shfl_down_sync(0xFFFFFFFFu, best, off);
            if (ot > best) best = ot;
        }
    }

    if (lane == 0) {
        const float t0 = p[0 * NCELL];
        const float t1 = p[1 * NCELL];
        const float t2 = p[2 * NCELL];
        const float t3 = p[3 * NCELL];

        const float conf  = __uint_as_float((unsigned int)(key >> 32) & 0x7FFFFFFFu);
        const float x_off = (float)((n >> 6) & 63);
        const float y_off = (float)(n & 63);
        const float cx = t0 + x_off, cy = t1 + y_off;
        const float hw = t2 * 0.5f,  hh = t3 * 0.5f;
        const float c0 = cx - hw, c1 = cy - hh, c2 = cx + hw, c3 = cy + hh;

        const int   bi = 255 - (int)(best & 0xFFull);
        const float bv = __uint_as_float(inv_ord((unsigned int)(best >> 32)));

        float* o = g_srt + ((size_t)b * TOPK + rk) * 8;
        *(float4*)(o)     = make_float4(c0, c1, c2, c3);
        *(float4*)(o + 4) = make_float4(conf, bv, (float)bi, 0.f);

        const float sh = (float)bi * CLS_OFF;
        g_box[(size_t)b * TOPK + rk]  = make_float4(c0 + sh, c1 + sh, c2 + sh, c3 + sh);
        g_area[(size_t)b * TOPK + rk] = (c2 - c0) * (c3 - c1);
    }
}

// ================= K3: IoU mask — upper-triangle pairs + rowblock summary =========
__global__ void __launch_bounds__(1024) mask_kernel() {
    __shared__ float4 sbox[TOPK];
    __shared__ float  sarea[TOPK];
    const int b = blockIdx.y;
    const int tid = threadIdx.x;

    sbox[tid]  = g_box[(size_t)b * TOPK + tid];
    sarea[tid] = g_area[(size_t)b * TOPK + tid];
    __syncthreads();

    const int p = blockIdx.x * 32 + (tid >> 5);   // pair index
    if (p >= NPAIRS) return;

    const float rt = sqrtf(4225.0f - 8.0f * (float)p);
    int qb = (int)((65.0f - rt) * 0.5f);
    if (tri_off(qb + 1) <= p) qb++;
    if (tri_off(qb) > p) qb--;
    const int w = qb + (p - tri_off(qb));
    const int lane = tid & 31;
    const int q = (qb << 5) | lane;

    const float4 bx   = sbox[q];
    const float  myAe = sarea[q] + 1e-9f;
    const int j0 = w << 5;

    unsigned int bits = 0;
    #pragma unroll 8
    for (int jj = 0; jj < 32; ++jj) {
        const int j = j0 + jj;
        const float4 ob = sbox[j];
        const float lx = fmaxf(bx.x, ob.x);
        const float ly = fmaxf(bx.y, ob.y);
        const float rx = fminf(bx.z, ob.z);
        const float ry = fminf(bx.w, ob.w);
        const float iw = fmaxf(rx - lx, 0.0f);
        const float ih = fmaxf(ry - ly, 0.0f);
        const float inter = iw * ih;
        const float denom = myAe + sarea[j] - inter;
        const bool hit = (denom > 0.0f) && (inter > IOU_THR * denom);
        if (hit) bits |= (1u << jj);
    }
    // diagonal word: clear bits jj <= lane (only j > q may suppress)
    if (w == qb) bits &= ~((2u << lane) - 1u);
    g_mask[((size_t)b * TOPK + q) * 32 + w] = bits;
    if (bits) atomicOr(&g_any[b * 32 + qb], bits);   // rowblock-nonzero summary
}

// ================= K4: greedy (sparse fast-path) + output =================
#define GREEDY_SMEM (TOPK * 32 * 4)   // 128 KB worst case; usually almost none touched
__global__ void __launch_bounds__(1024) greedy_kernel(float* __restrict__ out) {
    extern __shared__ unsigned int smask[];
    __shared__ unsigned int svalid[32];
    __shared__ unsigned int skeepw[32];
    __shared__ unsigned int sany[32];

    const int b = blockIdx.x, tid = threadIdx.x;
    const int w = tid >> 5, lane = tid & 31;

    if (tid < 32) sany[tid] = g_any[b * 32 + tid];
    __syncthreads();
    if (tid < 32) g_any[b * 32 + tid] = 0u;   // reset for next replay

    // conditional staging: warp w stages rowblock w (1024 uints = 256 uint4) iff nonzero
    if (sany[w]) {
        const uint4* src = (const uint4*)(g_mask + (size_t)b * TOPK * 32 + w * 1024);
        uint4* dst = (uint4*)(smask + w * 1024);
        #pragma unroll
        for (int k = 0; k < 8; ++k) dst[lane + k * 32] = src[lane + k * 32];
    }

    const float* o = g_srt + ((size_t)b * TOPK + tid) * 8;
    const float4 lo = *(const float4*)(o);
    const float4 hi = *(const float4*)(o + 4);
    const unsigned int bal = __ballot_sync(0xFFFFFFFFu, hi.x > CNF_THR);
    if (lane == 0) svalid[w] = bal;
    __syncthreads();

    if (tid < 32) {
        unsigned int sup = 0, keepw = 0;
        for (int blk = 0; blk < 32; ++blk) {
            const unsigned int ext = __shfl_sync(0xFFFFFFFFu, sup, blk);
            const unsigned int vv  = svalid[blk];

            unsigned int keepmask;
            if (sany[blk] == 0) {
                // no suppression bits anywhere in this rowblock:
                // every valid, not-yet-suppressed candidate is kept; sup unchanged
                keepmask = vv & ~ext;
            } else {
                keepmask = 0;
                if (tid == 0) {
                    unsigned int rr[32];
                    #pragma unroll
                    for (int i = 0; i < 32; ++i)
                        rr[i] = smask[(blk * 32 + i) * 32 + blk];
                    unsigned int s = ext;
                    #pragma unroll
                    for (int i = 0; i < 32; ++i) {     // branch-free greedy step
                        const unsigned int kb = ((~s >> i) & (vv >> i)) & 1u;
                        keepmask |= kb << i;
                        s |= rr[i] & (0u - kb);
                    }
                }
                keepmask = __shfl_sync(0xFFFFFFFFu, keepmask, 0);
                #pragma unroll
                for (int i = 0; i < 32; ++i)
                    sup |= smask[(blk * 32 + i) * 32 + tid] & (0u - ((keepmask >> i) & 1u));
            }
            if (tid == blk) keepw = keepmask;
        }
        skeepw[tid] = keepw;
    }
    __syncthreads();

    const bool kp = (skeepw[w] >> lane) & 1u;
    const float f = kp ? STRIDE_S : 0.0f;
    float* od = out + ((size_t)b * TOPK + tid) * 7;
    od[0] = f * lo.x; od[1] = f * lo.y; od[2] = f * lo.z; od[3] = f * lo.w;
    od[4] = f * hi.x; od[5] = f * hi.y; od[6] = f * hi.z;
    out[(size_t)B_IMGS * TOPK * 7 + (size_t)b * TOPK + tid] = kp ? 1.0f : 0.0f;
}

// ================= launcher =================
extern "C" void kernel_launch(void* const* d_in, const int* in_sizes, int n_in,
                              void* d_out, int out_size) {
    const float* in = (const float*)d_in[0];
    float* out = (float*)d_out;

    cudaFuncSetAttribute(greedy_kernel, cudaFuncAttributeMaxDynamicSharedMemorySize,
                         GREEDY_SMEM);

    select_kernel<<<B_IMGS, 1024>>>(in);
    rank_kernel<<<dim3(64, B_IMGS), 1024>>>(in);
    mask_kernel<<<dim3((NPAIRS + 31) / 32, B_IMGS), 1024>>>();
    greedy_kernel<<<B_IMGS, 1024, GREEDY_SMEM>>>(out);
}